// round 9
// baseline (speedup 1.0000x reference)
#include <cuda_runtime.h>
#include <cuda_bf16.h>
#include <cstdint>

// ============================================================================
// Split-bf16 (hi/lo) HMMA pipeline. Every GEMM is NT:
//   D[m][n] = sum_k A[m][k]*B[n][k],  D ~= AhBh + AhBl + AlBh  (fp32 accum)
// CTA tile 256x128x64, 8 warps (4Mx2N, 64x64 each), 2-stage cp.async pipe.
// K-axis stored 16-group PERMUTED (0,1,8,9,2,3,10,11,...) so each mma
// fragment pair is one LDS.64. smem XOR-swizzled (8B slot ^= (row&3)<<2),
// 128B rows, no padding -> conflict-free LDS.64, 192KB smem.
// ============================================================================

#define A_TILE_BYTES 32768               // 256 rows x 128B
#define B_TILE_BYTES 16384               // 128 rows x 128B
#define STG_BYTES (2 * A_TILE_BYTES + 2 * B_TILE_BYTES)   // 98304
#define SMEM_REQ (2 * STG_BYTES)         // 196608
#define OFF_AL A_TILE_BYTES
#define OFF_BH (2 * A_TILE_BYTES)
#define OFF_BL (2 * A_TILE_BYTES + B_TILE_BYTES)

// ---- scratch (device globals) ----------------------------------------------
__device__ __align__(256) __nv_bfloat16 g_xT_hi[33554432],  g_xT_lo[33554432];
__device__ __align__(256) __nv_bfloat16 g_Wqkv_hi[50331648],g_Wqkv_lo[50331648];
__device__ __align__(256) __nv_bfloat16 g_Wq_hi[16777216],  g_Wq_lo[16777216];
__device__ __align__(256) __nv_bfloat16 g_Wk_hi[16777216],  g_Wk_lo[16777216];
__device__ __align__(256) __nv_bfloat16 g_Wv_hi[16777216],  g_Wv_lo[16777216];
__device__ __align__(256) __nv_bfloat16 g_Wout_hi[16777216],g_Wout_lo[16777216];
__device__ __align__(256) __nv_bfloat16 g_qkv_hi[100663296],g_qkv_lo[100663296];
__device__ __align__(256) __nv_bfloat16 g_q2_hi[33554432],  g_q2_lo[33554432];
__device__ __align__(256) __nv_bfloat16 g_k2_hi[33554432],  g_k2_lo[33554432];
__device__ __align__(256) __nv_bfloat16 g_v2T_hi[33554432], g_v2T_lo[33554432];
__device__ __align__(256) __nv_bfloat16 g_attn_hi[4194304], g_attn_lo[4194304];
__device__ __align__(256) __nv_bfloat16 g_outT_hi[33554432],g_outT_lo[33554432];
__device__ __align__(256) float g_dot[4194304];

// ---- helpers ----------------------------------------------------------------
__device__ __forceinline__ uint32_t smem_u32(const void* p) {
    uint32_t r;
    asm("{ .reg .u64 t; cvta.to.shared.u64 t, %1; cvt.u32.u64 %0, t; }" : "=r"(r) : "l"(p));
    return r;
}
__device__ __forceinline__ void cpasync16(uint32_t dst, const void* src) {
    asm volatile("cp.async.cg.shared.global [%0], [%1], 16;" :: "r"(dst), "l"(src));
}
__device__ __forceinline__ void mma16816(float* c, const uint32_t* a, const uint32_t* b) {
    asm volatile(
        "mma.sync.aligned.m16n8k16.row.col.f32.bf16.bf16.f32 "
        "{%0,%1,%2,%3}, {%4,%5,%6,%7}, {%8,%9}, {%0,%1,%2,%3};"
        : "+f"(c[0]), "+f"(c[1]), "+f"(c[2]), "+f"(c[3])
        : "r"(a[0]), "r"(a[1]), "r"(a[2]), "r"(a[3]), "r"(b[0]), "r"(b[1]));
}
__device__ __forceinline__ void split2(float a, float b, uint32_t& hi, uint32_t& lo) {
    __nv_bfloat16 h0 = __float2bfloat16_rn(a), h1 = __float2bfloat16_rn(b);
    __nv_bfloat16 l0 = __float2bfloat16_rn(a - __bfloat162float(h0));
    __nv_bfloat16 l1 = __float2bfloat16_rn(b - __bfloat162float(h1));
    hi = (uint32_t)__bfloat16_as_ushort(h0) | ((uint32_t)__bfloat16_as_ushort(h1) << 16);
    lo = (uint32_t)__bfloat16_as_ushort(l0) | ((uint32_t)__bfloat16_as_ushort(l1) << 16);
}
// K permutation within 16-groups: k-order 0,1,8,9,2,3,10,11,4,5,12,13,6,7,14,15
__device__ __host__ __forceinline__ int permEven(int p) {   // p even, 0..14
    int q = p >> 1;
    return ((((q & 3) << 1) | (q >> 2)) << 1);
}
__device__ __forceinline__ int perm16(int p) {              // any p 0..15
    return permEven(p & 14) | (p & 1);
}

// ---- GEMM -------------------------------------------------------------------
struct GemmP {
    int nk, ldA, ldB, zshift, zmask;
    int aZ1, aZ2, aConst;          // A row offset = aZ1*zh + aZ2*zl + aConst
    int bZ1, bZ2, bConst;
    long long cZ1, cZ2;            // C element offset
    int ldC, biasMode, outMode;    // bias: 0 none 1 perM 2 perN; out: 0 f32 1 split
    const float* bias;
    float* Cf;
    __nv_bfloat16* Chi; __nv_bfloat16* Clo;
    float alpha;
};

__global__ void __launch_bounds__(256, 1)
hmma_gemm(const __nv_bfloat16* __restrict__ Ahg, const __nv_bfloat16* __restrict__ Alg,
          const __nv_bfloat16* __restrict__ Bhg, const __nv_bfloat16* __restrict__ Blg,
          const GemmP p)
{
    extern __shared__ __align__(16) char sm[];   // [2 stages]
    const int tid = threadIdx.x, lane = tid & 31, wid = tid >> 5;
    const int wm = (wid >> 1) * 64, wn = (wid & 1) * 64;
    const int zh = blockIdx.z >> p.zshift, zl = blockIdx.z & p.zmask;
    const long long arow0 = (long long)p.aZ1 * zh + p.aZ2 * zl + p.aConst
                            + (long long)blockIdx.y * 256;
    const long long brow0 = (long long)p.bZ1 * zh + p.bZ2 * zl + p.bConst
                            + (long long)blockIdx.x * 128;
    const __nv_bfloat16* gAh = Ahg + arow0 * p.ldA;
    const __nv_bfloat16* gAl = Alg + arow0 * p.ldA;
    const __nv_bfloat16* gBh = Bhg + brow0 * p.ldB;
    const __nv_bfloat16* gBl = Blg + brow0 * p.ldB;
    const uint32_t smbase = smem_u32(sm);

    const int ldA = p.ldA, ldB = p.ldB, nk = p.nk;

    auto load_stage = [&](int st, int kb) {
        const uint32_t sb = smbase + (uint32_t)st * STG_BYTES;
        const long long koff = (long long)kb * 64;
        // A tiles: 256 rows x 8 chunks(16B) = 2048 chunks per tile
#pragma unroll
        for (int i = 0; i < 8; i++) {
            const int c = tid + i * 256;
            const int row = c >> 3, ch = c & 7;
            const uint32_t doff = (uint32_t)(row * 128 +
                                  (((2 * ch) ^ ((row & 3) << 2)) << 3));
            const long long ga = (long long)row * ldA + koff + ch * 8;
            cpasync16(sb + doff, gAh + ga);
            cpasync16(sb + OFF_AL + doff, gAl + ga);
        }
        // B tiles: 128 rows x 8 chunks = 1024 chunks per tile
#pragma unroll
        for (int i = 0; i < 4; i++) {
            const int c = tid + i * 256;
            const int row = c >> 3, ch = c & 7;
            const uint32_t doff = (uint32_t)(row * 128 +
                                  (((2 * ch) ^ ((row & 3) << 2)) << 3));
            const long long gb = (long long)row * ldB + koff + ch * 8;
            cpasync16(sb + OFF_BH + doff, gBh + gb);
            cpasync16(sb + OFF_BL + doff, gBl + gb);
        }
        asm volatile("cp.async.commit_group;" ::: "memory");
    };

    load_stage(0, 0);
    load_stage(1, 1);

    float acc[4][8][4];
#pragma unroll
    for (int a = 0; a < 4; a++)
#pragma unroll
        for (int b = 0; b < 8; b++)
#pragma unroll
            for (int c = 0; c < 4; c++) acc[a][b][c] = 0.0f;

    const int kl = lane & 3;             // k quarter
    const int grow = lane >> 2;          // row within 8
    const int swx = (grow & 3) << 2;     // smem slot xor

    for (int kb = 0; kb < nk; kb++) {
        asm volatile("cp.async.wait_group 1;" ::: "memory");
        __syncthreads();
        const int st = kb & 1;
        const char* sAh = sm + (size_t)st * STG_BYTES;
        const char* sAl = sAh + A_TILE_BYTES;
        const char* sBh = sAl + A_TILE_BYTES;
        const char* sBl = sBh + B_TILE_BYTES;

#pragma unroll
        for (int k16 = 0; k16 < 4; k16++) {
            // swizzled byte offset within a row for this thread's 8B pair
            const uint32_t kOff = (uint32_t)(((k16 * 4 + kl) ^ swx) << 3);
            // ---- A fragments for all 4 mt (hi & lo) ----
            uint32_t ah[4][4], al[4][4];
#pragma unroll
            for (int mt = 0; mt < 4; mt++) {
                const uint32_t r0 = (uint32_t)(wm + mt * 16 + grow) * 128 + kOff;
                const uint32_t r1 = r0 + 8 * 128;
                uint2 v;
                v = *(const uint2*)(sAh + r0); ah[mt][0] = v.x; ah[mt][2] = v.y;
                v = *(const uint2*)(sAh + r1); ah[mt][1] = v.x; ah[mt][3] = v.y;
                v = *(const uint2*)(sAl + r0); al[mt][0] = v.x; al[mt][2] = v.y;
                v = *(const uint2*)(sAl + r1); al[mt][1] = v.x; al[mt][3] = v.y;
            }
            // ---- per nt: one LDS.64 each for Bh/Bl, reuse across mt ----
#pragma unroll
            for (int nt = 0; nt < 8; nt++) {
                const uint32_t rb = (uint32_t)(wn + nt * 8 + grow) * 128 + kOff;
                uint2 vh = *(const uint2*)(sBh + rb);
                uint2 vl = *(const uint2*)(sBl + rb);
                uint32_t bh[2] = {vh.x, vh.y};
                uint32_t bl[2] = {vl.x, vl.y};
#pragma unroll
                for (int mt = 0; mt < 4; mt++) {
                    mma16816(acc[mt][nt], ah[mt], bh);
                    mma16816(acc[mt][nt], ah[mt], bl);
                    mma16816(acc[mt][nt], al[mt], bh);
                }
            }
        }
        __syncthreads();
        if (kb + 2 < nk) load_stage(st, kb + 2);
    }

    // ---- epilogue ----
    const long long cbase = p.cZ1 * zh + p.cZ2 * zl;
    const int n0 = blockIdx.x * 128 + wn + kl * 2;
    const int m0 = blockIdx.y * 256 + wm + grow;
#pragma unroll
    for (int mt = 0; mt < 4; mt++) {
#pragma unroll
        for (int half = 0; half < 2; half++) {
            const int m = m0 + mt * 16 + half * 8;
            const float bm = (p.biasMode == 1) ? p.bias[m] : 0.0f;
            const long long rowoff = cbase + (long long)m * p.ldC;
#pragma unroll
            for (int nt = 0; nt < 8; nt++) {
                const int n = n0 + nt * 8;
                float v0 = acc[mt][nt][half * 2 + 0] * p.alpha + bm;
                float v1 = acc[mt][nt][half * 2 + 1] * p.alpha + bm;
                if (p.biasMode == 2) { v0 += p.bias[n]; v1 += p.bias[n + 1]; }
                if (p.outMode == 0) {
                    *(float2*)(p.Cf + rowoff + n) = make_float2(v0, v1);
                } else {
                    // store K-permuted for the next GEMM
                    const int np = (n & ~15) | permEven(n & 15);
                    uint32_t h, l;
                    split2(v0, v1, h, l);
                    *(uint32_t*)(p.Chi + rowoff + np) = h;
                    *(uint32_t*)(p.Clo + rowoff + np) = l;
                }
            }
        }
    }
}

// ---- conversions (all write K-permuted layouts) ------------------------------
// one thread = one 16-element K-group: permuted pair order 0,4,1,5,2,6,3,7
__global__ void split_perm_kernel(const float4* __restrict__ in,
                                  uint2* __restrict__ hi, uint2* __restrict__ lo,
                                  int n16)
{
    int i = blockIdx.x * 256 + threadIdx.x;
    if (i >= n16) return;
    const float4* f = in + (size_t)i * 4;
    float4 v0 = f[0], v1 = f[1], v2 = f[2], v3 = f[3];
    uint32_t ph[8], pl[8];
    split2(v0.x, v0.y, ph[0], pl[0]); split2(v0.z, v0.w, ph[1], pl[1]);
    split2(v1.x, v1.y, ph[2], pl[2]); split2(v1.z, v1.w, ph[3], pl[3]);
    split2(v2.x, v2.y, ph[4], pl[4]); split2(v2.z, v2.w, ph[5], pl[5]);
    split2(v3.x, v3.y, ph[6], pl[6]); split2(v3.z, v3.w, ph[7], pl[7]);
    uint2* dh = hi + (size_t)i * 4;
    uint2* dl = lo + (size_t)i * 4;
    dh[0] = make_uint2(ph[0], ph[4]); dl[0] = make_uint2(pl[0], pl[4]);
    dh[1] = make_uint2(ph[1], ph[5]); dl[1] = make_uint2(pl[1], pl[5]);
    dh[2] = make_uint2(ph[2], ph[6]); dl[2] = make_uint2(pl[2], pl[6]);
    dh[3] = make_uint2(ph[3], ph[7]); dl[3] = make_uint2(pl[3], pl[7]);
}

// x[b][c][n] fp32 -> xT[b][n][c] split bf16, c-axis (K) permuted
__global__ void transpose_split_kernel(const float* __restrict__ x,
                                       __nv_bfloat16* __restrict__ hi,
                                       __nv_bfloat16* __restrict__ lo)
{
    __shared__ float tile[32][33];
    const int b = blockIdx.z;
    const int c0 = blockIdx.y * 32, n0 = blockIdx.x * 32;
    const int tx = threadIdx.x, ty = threadIdx.y;
    const float* xb = x + (long long)b * 16777216;
#pragma unroll
    for (int i = 0; i < 4; i++)
        tile[ty + i * 8][tx] = xb[(long long)(c0 + ty + i * 8) * 4096 + n0 + tx];
    __syncthreads();
    const int cp = (tx & ~15) | perm16(tx & 15);   // permuted low 5 bits of c
#pragma unroll
    for (int i = 0; i < 4; i++) {
        float v = tile[tx][ty + i * 8];
        __nv_bfloat16 h = __float2bfloat16_rn(v);
        __nv_bfloat16 l = __float2bfloat16_rn(v - __bfloat162float(h));
        long long o = (long long)b * 16777216 + (long long)(n0 + ty + i * 8) * 4096 + c0 + cp;
        hi[o] = h; lo[o] = l;
    }
}

// softmax over rows of 512, output split bf16 with permuted cols
__global__ void softmax_split_kernel(const float* __restrict__ dot,
                                     __nv_bfloat16* __restrict__ hi,
                                     __nv_bfloat16* __restrict__ lo)
{
    const long long row = blockIdx.x;
    const float* p = dot + row * 512;
    __shared__ float red[256];
    const int t = threadIdx.x;
    float v0 = p[t], v1 = p[t + 256];
    red[t] = fmaxf(v0, v1); __syncthreads();
#pragma unroll
    for (int s = 128; s > 0; s >>= 1) {
        if (t < s) red[t] = fmaxf(red[t], red[t + s]);
        __syncthreads();
    }
    float mx = red[0]; __syncthreads();
    float e0 = expf(v0 - mx), e1 = expf(v1 - mx);
    red[t] = e0 + e1; __syncthreads();
#pragma unroll
    for (int s = 128; s > 0; s >>= 1) {
        if (t < s) red[t] += red[t + s];
        __syncthreads();
    }
    float inv = 1.0f / red[0];
    float a0 = e0 * inv, a1 = e1 * inv;
    const int tp0 = (t & ~15) | perm16(t & 15);
    const int tp1 = ((t + 256) & ~15) | perm16((t + 256) & 15);
    __nv_bfloat16 h0 = __float2bfloat16_rn(a0);
    __nv_bfloat16 h1 = __float2bfloat16_rn(a1);
    hi[row * 512 + tp0] = h0;
    hi[row * 512 + tp1] = h1;
    lo[row * 512 + tp0] = __float2bfloat16_rn(a0 - __bfloat162float(h0));
    lo[row * 512 + tp1] = __float2bfloat16_rn(a1 - __bfloat162float(h1));
}

// ---- host --------------------------------------------------------------------
extern "C" void kernel_launch(void* const* d_in, const int* in_sizes, int n_in,
                              void* d_out, int out_size)
{
    const float* x    = (const float*)d_in[0];
    const float* Wqkv = (const float*)d_in[1];
    const float* bqkv = (const float*)d_in[2];
    const float* Wq   = (const float*)d_in[3];
    const float* bq   = (const float*)d_in[4];
    const float* Wk   = (const float*)d_in[5];
    const float* bk   = (const float*)d_in[6];
    const float* Wv   = (const float*)d_in[7];
    const float* bv   = (const float*)d_in[8];
    const float* Wout = (const float*)d_in[9];
    const float* bout = (const float*)d_in[10];
    float* y = (float*)d_out;

    __nv_bfloat16 *xT_h, *xT_l, *Wqkv_h, *Wqkv_l, *Wq_h, *Wq_l, *Wk_h, *Wk_l,
        *Wv_h, *Wv_l, *Wout_h, *Wout_l, *qkv_h, *qkv_l, *q2_h, *q2_l,
        *k2_h, *k2_l, *v2T_h, *v2T_l, *attn_h, *attn_l, *outT_h, *outT_l;
    float* dot;
    cudaGetSymbolAddress((void**)&xT_h,   g_xT_hi);   cudaGetSymbolAddress((void**)&xT_l,   g_xT_lo);
    cudaGetSymbolAddress((void**)&Wqkv_h, g_Wqkv_hi); cudaGetSymbolAddress((void**)&Wqkv_l, g_Wqkv_lo);
    cudaGetSymbolAddress((void**)&Wq_h,   g_Wq_hi);   cudaGetSymbolAddress((void**)&Wq_l,   g_Wq_lo);
    cudaGetSymbolAddress((void**)&Wk_h,   g_Wk_hi);   cudaGetSymbolAddress((void**)&Wk_l,   g_Wk_lo);
    cudaGetSymbolAddress((void**)&Wv_h,   g_Wv_hi);   cudaGetSymbolAddress((void**)&Wv_l,   g_Wv_lo);
    cudaGetSymbolAddress((void**)&Wout_h, g_Wout_hi); cudaGetSymbolAddress((void**)&Wout_l, g_Wout_lo);
    cudaGetSymbolAddress((void**)&qkv_h,  g_qkv_hi);  cudaGetSymbolAddress((void**)&qkv_l,  g_qkv_lo);
    cudaGetSymbolAddress((void**)&q2_h,   g_q2_hi);   cudaGetSymbolAddress((void**)&q2_l,   g_q2_lo);
    cudaGetSymbolAddress((void**)&k2_h,   g_k2_hi);   cudaGetSymbolAddress((void**)&k2_l,   g_k2_lo);
    cudaGetSymbolAddress((void**)&v2T_h,  g_v2T_hi);  cudaGetSymbolAddress((void**)&v2T_l,  g_v2T_lo);
    cudaGetSymbolAddress((void**)&attn_h, g_attn_hi); cudaGetSymbolAddress((void**)&attn_l, g_attn_lo);
    cudaGetSymbolAddress((void**)&outT_h, g_outT_hi); cudaGetSymbolAddress((void**)&outT_l, g_outT_lo);
    cudaGetSymbolAddress((void**)&dot,    g_dot);

    cudaFuncSetAttribute(hmma_gemm, cudaFuncAttributeMaxDynamicSharedMemorySize, SMEM_REQ);

    // conversions (K-permuted outputs)
    split_perm_kernel<<<12288, 256>>>((const float4*)Wqkv, (uint2*)Wqkv_h, (uint2*)Wqkv_l, 3145728);
    split_perm_kernel<<<4096, 256>>>((const float4*)Wq,   (uint2*)Wq_h,   (uint2*)Wq_l,   1048576);
    split_perm_kernel<<<4096, 256>>>((const float4*)Wk,   (uint2*)Wk_h,   (uint2*)Wk_l,   1048576);
    split_perm_kernel<<<4096, 256>>>((const float4*)Wv,   (uint2*)Wv_h,   (uint2*)Wv_l,   1048576);
    split_perm_kernel<<<4096, 256>>>((const float4*)Wout, (uint2*)Wout_h, (uint2*)Wout_l, 1048576);
    transpose_split_kernel<<<dim3(128, 128, 2), dim3(32, 8)>>>(x, xT_h, xT_l);

    GemmP p;
    // Stage 1: qkv[b] = Wqkv @ xT[b]^T + bqkv -> split qkv [2][12288][4096]
    p = {64, 4096, 4096, 0, 0,  0, 0, 0,  4096, 0, 0,  50331648LL, 0,
         4096, 1, 1, bqkv, nullptr, qkv_h, qkv_l, 1.0f};
    hmma_gemm<<<dim3(32, 48, 2), 256, SMEM_REQ>>>(Wqkv_h, Wqkv_l, xT_h, xT_l, p);

    // Stage 2q: q2[z] = qkv_q[z] @ Wq^T + bq   (z = b*8+h)
    p = {64, 4096, 4096, 3, 7,  12288, 512, 0,  0, 0, 0,  16777216LL, 2097152LL,
         4096, 2, 1, bq, nullptr, q2_h, q2_l, 1.0f};
    hmma_gemm<<<dim3(32, 2, 16), 256, SMEM_REQ>>>(qkv_h, qkv_l, Wq_h, Wq_l, p);
    // Stage 2k
    p = {64, 4096, 4096, 3, 7,  12288, 512, 4096,  0, 0, 0,  16777216LL, 2097152LL,
         4096, 2, 1, bk, nullptr, k2_h, k2_l, 1.0f};
    hmma_gemm<<<dim3(32, 2, 16), 256, SMEM_REQ>>>(qkv_h, qkv_l, Wk_h, Wk_l, p);
    // Stage 2v (transposed): v2T[b][h][m][d] = Wv[m] . v[z][d] + bv[m]
    p = {64, 4096, 4096, 3, 7,  0, 0, 0,  12288, 512, 8192,  16777216LL, 2097152LL,
         512, 1, 1, bv, nullptr, v2T_h, v2T_l, 1.0f};
    hmma_gemm<<<dim3(4, 16, 16), 256, SMEM_REQ>>>(Wv_h, Wv_l, qkv_h, qkv_l, p);

    // Stage 3: dot[z] = q2[z] @ k2[z]^T * 0.125 -> fp32 (no perm on fp32 out)
    p = {64, 4096, 4096, 3, 7,  4096, 512, 0,  4096, 512, 0,  2097152LL, 262144LL,
         512, 0, 0, nullptr, dot, nullptr, nullptr, 0.125f};
    hmma_gemm<<<dim3(4, 2, 16), 256, SMEM_REQ>>>(q2_h, q2_l, k2_h, k2_l, p);

    // Stage 4: softmax + split (permuted cols)
    softmax_split_kernel<<<8192, 256>>>(dot, attn_h, attn_l);

    // Stage 5 (transposed): outT[b][m][h*512+c] = v2T[z][m] . attn[z][c]
    p = {8, 512, 512, 3, 7,  32768, 4096, 0,  4096, 512, 0,  16777216LL, 512LL,
         4096, 0, 1, nullptr, nullptr, outT_h, outT_l, 1.0f};
    hmma_gemm<<<dim3(4, 16, 16), 256, SMEM_REQ>>>(v2T_h, v2T_l, attn_h, attn_l, p);

    // Stage 6: y[b] = Wout @ outT[b]^T + bout -> fp32 d_out (natural order)
    p = {64, 4096, 4096, 0, 0,  0, 0, 0,  4096, 0, 0,  16777216LL, 0,
         4096, 1, 0, bout, y, nullptr, nullptr, 1.0f};
    hmma_gemm<<<dim3(32, 16, 2), 256, SMEM_REQ>>>(Wout_h, Wout_l, outT_h, outT_l, p);

    (void)in_sizes; (void)n_in; (void)out_size;
}

// round 10
// speedup vs baseline: 1.0616x; 1.0616x over previous
#include <cuda_runtime.h>
#include <cuda_bf16.h>
#include <cstdint>

// ============================================================================
// Split-bf16 (hi/lo) HMMA pipeline. Every GEMM is NT:
//   D[m][n] = sum_k A[m][k]*B[n][k],  D ~= AhBh + AhBl + AlBh  (fp32 accum)
// mma.sync.m16n8k16 bf16. CTA tile 256x128x64, 8 warps (4Mx2N, 64x64 each),
// 2-stage cp.async pipeline, plain LDS fragment loads, MMAs pass-reordered
// (hh x4mt, hl x4mt, lh x4mt per nt) to break accumulator RAW chains.
// ============================================================================

#define PADK 72                          // 64 data + 8 pad bf16 (144B rows)
#define A_TILE_ELT (256 * PADK)          // 18432
#define B_TILE_ELT (128 * PADK)          // 9216
#define STG_ELT (2 * A_TILE_ELT + 2 * B_TILE_ELT)   // 55296 elements
#define STG_BYTES (STG_ELT * 2)          // 110592
#define SMEM_REQ (2 * STG_BYTES)         // 221184
#define OFF_AL (A_TILE_ELT * 2)
#define OFF_BH (2 * A_TILE_ELT * 2)
#define OFF_BL (2 * A_TILE_ELT * 2 + B_TILE_ELT * 2)

// ---- scratch (device globals) ----------------------------------------------
__device__ __align__(256) __nv_bfloat16 g_xT_hi[33554432],  g_xT_lo[33554432];
__device__ __align__(256) __nv_bfloat16 g_Wqkv_hi[50331648],g_Wqkv_lo[50331648];
__device__ __align__(256) __nv_bfloat16 g_Wq_hi[16777216],  g_Wq_lo[16777216];
__device__ __align__(256) __nv_bfloat16 g_Wk_hi[16777216],  g_Wk_lo[16777216];
__device__ __align__(256) __nv_bfloat16 g_Wv_hi[16777216],  g_Wv_lo[16777216];
__device__ __align__(256) __nv_bfloat16 g_Wout_hi[16777216],g_Wout_lo[16777216];
__device__ __align__(256) __nv_bfloat16 g_qkv_hi[100663296],g_qkv_lo[100663296];
__device__ __align__(256) __nv_bfloat16 g_q2_hi[33554432],  g_q2_lo[33554432];
__device__ __align__(256) __nv_bfloat16 g_k2_hi[33554432],  g_k2_lo[33554432];
__device__ __align__(256) __nv_bfloat16 g_v2T_hi[33554432], g_v2T_lo[33554432];
__device__ __align__(256) __nv_bfloat16 g_attn_hi[4194304], g_attn_lo[4194304];
__device__ __align__(256) __nv_bfloat16 g_outT_hi[33554432],g_outT_lo[33554432];
__device__ __align__(256) float g_dot[4194304];

// ---- helpers ----------------------------------------------------------------
__device__ __forceinline__ uint32_t smem_u32(const void* p) {
    uint32_t r;
    asm("{ .reg .u64 t; cvta.to.shared.u64 t, %1; cvt.u32.u64 %0, t; }" : "=r"(r) : "l"(p));
    return r;
}
__device__ __forceinline__ void cpasync16(uint32_t dst, const void* src) {
    asm volatile("cp.async.cg.shared.global [%0], [%1], 16;" :: "r"(dst), "l"(src));
}
__device__ __forceinline__ void mma16816(float* c, const uint32_t* a, const uint32_t* b) {
    asm volatile(
        "mma.sync.aligned.m16n8k16.row.col.f32.bf16.bf16.f32 "
        "{%0,%1,%2,%3}, {%4,%5,%6,%7}, {%8,%9}, {%0,%1,%2,%3};"
        : "+f"(c[0]), "+f"(c[1]), "+f"(c[2]), "+f"(c[3])
        : "r"(a[0]), "r"(a[1]), "r"(a[2]), "r"(a[3]), "r"(b[0]), "r"(b[1]));
}
__device__ __forceinline__ void split2(float a, float b, uint32_t& hi, uint32_t& lo) {
    __nv_bfloat16 h0 = __float2bfloat16_rn(a), h1 = __float2bfloat16_rn(b);
    __nv_bfloat16 l0 = __float2bfloat16_rn(a - __bfloat162float(h0));
    __nv_bfloat16 l1 = __float2bfloat16_rn(b - __bfloat162float(h1));
    hi = (uint32_t)__bfloat16_as_ushort(h0) | ((uint32_t)__bfloat16_as_ushort(h1) << 16);
    lo = (uint32_t)__bfloat16_as_ushort(l0) | ((uint32_t)__bfloat16_as_ushort(l1) << 16);
}

// ---- GEMM -------------------------------------------------------------------
struct GemmP {
    int nk, ldA, ldB, zshift, zmask;
    int aZ1, aZ2, aConst;          // A row offset = aZ1*zh + aZ2*zl + aConst
    int bZ1, bZ2, bConst;
    long long cZ1, cZ2;            // C element offset
    int ldC, biasMode, outMode;    // bias: 0 none 1 perM 2 perN; out: 0 f32 1 split
    const float* bias;
    float* Cf;
    __nv_bfloat16* Chi; __nv_bfloat16* Clo;
    float alpha;
};

__global__ void __launch_bounds__(256, 1)
hmma_gemm(const __nv_bfloat16* __restrict__ Ahg, const __nv_bfloat16* __restrict__ Alg,
          const __nv_bfloat16* __restrict__ Bhg, const __nv_bfloat16* __restrict__ Blg,
          const GemmP p)
{
    extern __shared__ __align__(16) __nv_bfloat16 sm[];   // [2 stages]
    const int tid = threadIdx.x, lane = tid & 31, wid = tid >> 5;
    const int wm = (wid >> 1) * 64, wn = (wid & 1) * 64;
    const int zh = blockIdx.z >> p.zshift, zl = blockIdx.z & p.zmask;
    const long long arow0 = (long long)p.aZ1 * zh + p.aZ2 * zl + p.aConst
                            + (long long)blockIdx.y * 256;
    const long long brow0 = (long long)p.bZ1 * zh + p.bZ2 * zl + p.bConst
                            + (long long)blockIdx.x * 128;
    const __nv_bfloat16* gAh = Ahg + arow0 * p.ldA;
    const __nv_bfloat16* gAl = Alg + arow0 * p.ldA;
    const __nv_bfloat16* gBh = Bhg + brow0 * p.ldB;
    const __nv_bfloat16* gBl = Blg + brow0 * p.ldB;
    const uint32_t smbase = smem_u32(sm);

    const int ldA = p.ldA, ldB = p.ldB, nk = p.nk;

    auto load_stage = [&](int st, int kb) {
        const uint32_t sb = smbase + (uint32_t)st * STG_BYTES;
        const long long koff = (long long)kb * 64;
        // A tiles: 256 rows x 8 chunks = 2048 chunks per type
#pragma unroll
        for (int i = 0; i < 8; i++) {
            const int c = tid + i * 256;
            const int row = c >> 3, ch = c & 7;
            const uint32_t doff = (uint32_t)(row * PADK + ch * 8) * 2;
            const long long ga = (long long)row * ldA + koff + ch * 8;
            cpasync16(sb + doff, gAh + ga);
            cpasync16(sb + OFF_AL + doff, gAl + ga);
        }
        // B tiles: 128 rows x 8 chunks = 1024 chunks per type
#pragma unroll
        for (int i = 0; i < 4; i++) {
            const int c = tid + i * 256;
            const int row = c >> 3, ch = c & 7;
            const uint32_t doff = (uint32_t)(row * PADK + ch * 8) * 2;
            const long long gb = (long long)row * ldB + koff + ch * 8;
            cpasync16(sb + OFF_BH + doff, gBh + gb);
            cpasync16(sb + OFF_BL + doff, gBl + gb);
        }
        asm volatile("cp.async.commit_group;" ::: "memory");
    };

    // prologue: 2 stages in flight (all stages have nk >= 2)
    load_stage(0, 0);
    load_stage(1, 1);

    float acc[4][8][4];
#pragma unroll
    for (int a = 0; a < 4; a++)
#pragma unroll
        for (int b = 0; b < 8; b++)
#pragma unroll
            for (int c = 0; c < 4; c++) acc[a][b][c] = 0.0f;

    const int krow = (lane & 3) * 2;     // k within 16
    const int grow = lane >> 2;          // row within 8

    for (int kb = 0; kb < nk; kb++) {
        asm volatile("cp.async.wait_group 1;" ::: "memory");
        __syncthreads();
        const int st = kb & 1;
        const __nv_bfloat16* sAh = sm + (size_t)st * STG_ELT;
        const __nv_bfloat16* sAl = sAh + A_TILE_ELT;
        const __nv_bfloat16* sBh = sAl + A_TILE_ELT;
        const __nv_bfloat16* sBl = sBh + B_TILE_ELT;

#pragma unroll
        for (int k16 = 0; k16 < 4; k16++) {
            const int kk = k16 * 16 + krow;
            // ---- A fragments for all 4 mt (hi & lo) ----
            uint32_t ah[4][4], al[4][4];
#pragma unroll
            for (int mt = 0; mt < 4; mt++) {
                const int r0 = (wm + mt * 16 + grow) * PADK;
                const int r1 = r0 + 8 * PADK;
                ah[mt][0] = *(const uint32_t*)(sAh + r0 + kk);
                ah[mt][1] = *(const uint32_t*)(sAh + r1 + kk);
                ah[mt][2] = *(const uint32_t*)(sAh + r0 + kk + 8);
                ah[mt][3] = *(const uint32_t*)(sAh + r1 + kk + 8);
                al[mt][0] = *(const uint32_t*)(sAl + r0 + kk);
                al[mt][1] = *(const uint32_t*)(sAl + r1 + kk);
                al[mt][2] = *(const uint32_t*)(sAl + r0 + kk + 8);
                al[mt][3] = *(const uint32_t*)(sAl + r1 + kk + 8);
            }
            // ---- per nt: load B frag once; 3 passes over mt so consecutive
            //      writes to the same accumulator are 4 MMAs apart ----
#pragma unroll
            for (int nt = 0; nt < 8; nt++) {
                const int r = (wn + nt * 8 + grow) * PADK;
                uint32_t bh[2], bl[2];
                bh[0] = *(const uint32_t*)(sBh + r + kk);
                bh[1] = *(const uint32_t*)(sBh + r + kk + 8);
                bl[0] = *(const uint32_t*)(sBl + r + kk);
                bl[1] = *(const uint32_t*)(sBl + r + kk + 8);
#pragma unroll
                for (int mt = 0; mt < 4; mt++)
                    mma16816(acc[mt][nt], ah[mt], bh);
#pragma unroll
                for (int mt = 0; mt < 4; mt++)
                    mma16816(acc[mt][nt], ah[mt], bl);
#pragma unroll
                for (int mt = 0; mt < 4; mt++)
                    mma16816(acc[mt][nt], al[mt], bh);
            }
        }
        __syncthreads();
        if (kb + 2 < nk) load_stage(st, kb + 2);
    }

    // ---- epilogue ----
    const long long cbase = p.cZ1 * zh + p.cZ2 * zl;
    const int n0 = blockIdx.x * 128 + wn + (lane & 3) * 2;
    const int m0 = blockIdx.y * 256 + wm + (lane >> 2);
#pragma unroll
    for (int mt = 0; mt < 4; mt++) {
#pragma unroll
        for (int half = 0; half < 2; half++) {
            const int m = m0 + mt * 16 + half * 8;
            const float bm = (p.biasMode == 1) ? p.bias[m] : 0.0f;
            const long long rowoff = cbase + (long long)m * p.ldC;
#pragma unroll
            for (int nt = 0; nt < 8; nt++) {
                const int n = n0 + nt * 8;
                float v0 = acc[mt][nt][half * 2 + 0] * p.alpha + bm;
                float v1 = acc[mt][nt][half * 2 + 1] * p.alpha + bm;
                if (p.biasMode == 2) { v0 += p.bias[n]; v1 += p.bias[n + 1]; }
                if (p.outMode == 0) {
                    *(float2*)(p.Cf + rowoff + n) = make_float2(v0, v1);
                } else {
                    uint32_t h, l;
                    split2(v0, v1, h, l);
                    *(uint32_t*)(p.Chi + rowoff + n) = h;
                    *(uint32_t*)(p.Clo + rowoff + n) = l;
                }
            }
        }
    }
}

// ---- conversions -------------------------------------------------------------
__global__ void split_kernel(const float4* __restrict__ in, uint2* __restrict__ hi,
                             uint2* __restrict__ lo, int n4)
{
    int i = blockIdx.x * 256 + threadIdx.x;
    if (i >= n4) return;
    float4 v = in[i];
    uint32_t h0, l0, h1, l1;
    split2(v.x, v.y, h0, l0);
    split2(v.z, v.w, h1, l1);
    hi[i] = make_uint2(h0, h1);
    lo[i] = make_uint2(l0, l1);
}

// x[b][c][n] fp32 -> xT[b][n][c] split bf16 (4096x4096 per batch)
__global__ void transpose_split_kernel(const float* __restrict__ x,
                                       __nv_bfloat16* __restrict__ hi,
                                       __nv_bfloat16* __restrict__ lo)
{
    __shared__ float tile[32][33];
    const int b = blockIdx.z;
    const int c0 = blockIdx.y * 32, n0 = blockIdx.x * 32;
    const int tx = threadIdx.x, ty = threadIdx.y;
    const float* xb = x + (long long)b * 16777216;
#pragma unroll
    for (int i = 0; i < 4; i++)
        tile[ty + i * 8][tx] = xb[(long long)(c0 + ty + i * 8) * 4096 + n0 + tx];
    __syncthreads();
#pragma unroll
    for (int i = 0; i < 4; i++) {
        float v = tile[tx][ty + i * 8];
        __nv_bfloat16 h = __float2bfloat16_rn(v);
        __nv_bfloat16 l = __float2bfloat16_rn(v - __bfloat162float(h));
        long long o = (long long)b * 16777216 + (long long)(n0 + ty + i * 8) * 4096 + c0 + tx;
        hi[o] = h; lo[o] = l;
    }
}

// softmax over rows of 512, output split bf16
__global__ void softmax_split_kernel(const float* __restrict__ dot,
                                     __nv_bfloat16* __restrict__ hi,
                                     __nv_bfloat16* __restrict__ lo)
{
    const long long row = blockIdx.x;
    const float* p = dot + row * 512;
    __shared__ float red[256];
    const int t = threadIdx.x;
    float v0 = p[t], v1 = p[t + 256];
    red[t] = fmaxf(v0, v1); __syncthreads();
#pragma unroll
    for (int s = 128; s > 0; s >>= 1) {
        if (t < s) red[t] = fmaxf(red[t], red[t + s]);
        __syncthreads();
    }
    float mx = red[0]; __syncthreads();
    float e0 = expf(v0 - mx), e1 = expf(v1 - mx);
    red[t] = e0 + e1; __syncthreads();
#pragma unroll
    for (int s = 128; s > 0; s >>= 1) {
        if (t < s) red[t] += red[t + s];
        __syncthreads();
    }
    float inv = 1.0f / red[0];
    float a0 = e0 * inv, a1 = e1 * inv;
    __nv_bfloat16 h0 = __float2bfloat16_rn(a0);
    __nv_bfloat16 h1 = __float2bfloat16_rn(a1);
    hi[row * 512 + t]       = h0;
    hi[row * 512 + t + 256] = h1;
    lo[row * 512 + t]       = __float2bfloat16_rn(a0 - __bfloat162float(h0));
    lo[row * 512 + t + 256] = __float2bfloat16_rn(a1 - __bfloat162float(h1));
}

// ---- host --------------------------------------------------------------------
extern "C" void kernel_launch(void* const* d_in, const int* in_sizes, int n_in,
                              void* d_out, int out_size)
{
    const float* x    = (const float*)d_in[0];
    const float* Wqkv = (const float*)d_in[1];
    const float* bqkv = (const float*)d_in[2];
    const float* Wq   = (const float*)d_in[3];
    const float* bq   = (const float*)d_in[4];
    const float* Wk   = (const float*)d_in[5];
    const float* bk   = (const float*)d_in[6];
    const float* Wv   = (const float*)d_in[7];
    const float* bv   = (const float*)d_in[8];
    const float* Wout = (const float*)d_in[9];
    const float* bout = (const float*)d_in[10];
    float* y = (float*)d_out;

    __nv_bfloat16 *xT_h, *xT_l, *Wqkv_h, *Wqkv_l, *Wq_h, *Wq_l, *Wk_h, *Wk_l,
        *Wv_h, *Wv_l, *Wout_h, *Wout_l, *qkv_h, *qkv_l, *q2_h, *q2_l,
        *k2_h, *k2_l, *v2T_h, *v2T_l, *attn_h, *attn_l, *outT_h, *outT_l;
    float* dot;
    cudaGetSymbolAddress((void**)&xT_h,   g_xT_hi);   cudaGetSymbolAddress((void**)&xT_l,   g_xT_lo);
    cudaGetSymbolAddress((void**)&Wqkv_h, g_Wqkv_hi); cudaGetSymbolAddress((void**)&Wqkv_l, g_Wqkv_lo);
    cudaGetSymbolAddress((void**)&Wq_h,   g_Wq_hi);   cudaGetSymbolAddress((void**)&Wq_l,   g_Wq_lo);
    cudaGetSymbolAddress((void**)&Wk_h,   g_Wk_hi);   cudaGetSymbolAddress((void**)&Wk_l,   g_Wk_lo);
    cudaGetSymbolAddress((void**)&Wv_h,   g_Wv_hi);   cudaGetSymbolAddress((void**)&Wv_l,   g_Wv_lo);
    cudaGetSymbolAddress((void**)&Wout_h, g_Wout_hi); cudaGetSymbolAddress((void**)&Wout_l, g_Wout_lo);
    cudaGetSymbolAddress((void**)&qkv_h,  g_qkv_hi);  cudaGetSymbolAddress((void**)&qkv_l,  g_qkv_lo);
    cudaGetSymbolAddress((void**)&q2_h,   g_q2_hi);   cudaGetSymbolAddress((void**)&q2_l,   g_q2_lo);
    cudaGetSymbolAddress((void**)&k2_h,   g_k2_hi);   cudaGetSymbolAddress((void**)&k2_l,   g_k2_lo);
    cudaGetSymbolAddress((void**)&v2T_h,  g_v2T_hi);  cudaGetSymbolAddress((void**)&v2T_l,  g_v2T_lo);
    cudaGetSymbolAddress((void**)&attn_h, g_attn_hi); cudaGetSymbolAddress((void**)&attn_l, g_attn_lo);
    cudaGetSymbolAddress((void**)&outT_h, g_outT_hi); cudaGetSymbolAddress((void**)&outT_l, g_outT_lo);
    cudaGetSymbolAddress((void**)&dot,    g_dot);

    cudaFuncSetAttribute(hmma_gemm, cudaFuncAttributeMaxDynamicSharedMemorySize, SMEM_REQ);

    // conversions
    split_kernel<<<49152, 256>>>((const float4*)Wqkv, (uint2*)Wqkv_h, (uint2*)Wqkv_l, 12582912);
    split_kernel<<<16384, 256>>>((const float4*)Wq,   (uint2*)Wq_h,   (uint2*)Wq_l,   4194304);
    split_kernel<<<16384, 256>>>((const float4*)Wk,   (uint2*)Wk_h,   (uint2*)Wk_l,   4194304);
    split_kernel<<<16384, 256>>>((const float4*)Wv,   (uint2*)Wv_h,   (uint2*)Wv_l,   4194304);
    split_kernel<<<16384, 256>>>((const float4*)Wout, (uint2*)Wout_h, (uint2*)Wout_l, 4194304);
    transpose_split_kernel<<<dim3(128, 128, 2), dim3(32, 8)>>>(x, xT_h, xT_l);

    GemmP p;
    // Stage 1: qkv[b] = Wqkv @ xT[b]^T + bqkv -> split qkv [2][12288][4096]
    p = {64, 4096, 4096, 0, 0,  0, 0, 0,  4096, 0, 0,  50331648LL, 0,
         4096, 1, 1, bqkv, nullptr, qkv_h, qkv_l, 1.0f};
    hmma_gemm<<<dim3(32, 48, 2), 256, SMEM_REQ>>>(Wqkv_h, Wqkv_l, xT_h, xT_l, p);

    // Stage 2q: q2[z] = qkv_q[z] @ Wq^T + bq   (z = b*8+h)
    p = {64, 4096, 4096, 3, 7,  12288, 512, 0,  0, 0, 0,  16777216LL, 2097152LL,
         4096, 2, 1, bq, nullptr, q2_h, q2_l, 1.0f};
    hmma_gemm<<<dim3(32, 2, 16), 256, SMEM_REQ>>>(qkv_h, qkv_l, Wq_h, Wq_l, p);
    // Stage 2k
    p = {64, 4096, 4096, 3, 7,  12288, 512, 4096,  0, 0, 0,  16777216LL, 2097152LL,
         4096, 2, 1, bk, nullptr, k2_h, k2_l, 1.0f};
    hmma_gemm<<<dim3(32, 2, 16), 256, SMEM_REQ>>>(qkv_h, qkv_l, Wk_h, Wk_l, p);
    // Stage 2v (transposed): v2T[b][h][m][d] = Wv[m] . v[z][d] + bv[m]
    p = {64, 4096, 4096, 3, 7,  0, 0, 0,  12288, 512, 8192,  16777216LL, 2097152LL,
         512, 1, 1, bv, nullptr, v2T_h, v2T_l, 1.0f};
    hmma_gemm<<<dim3(4, 16, 16), 256, SMEM_REQ>>>(Wv_h, Wv_l, qkv_h, qkv_l, p);

    // Stage 3: dot[z] = q2[z] @ k2[z]^T * 0.125 -> fp32
    p = {64, 4096, 4096, 3, 7,  4096, 512, 0,  4096, 512, 0,  2097152LL, 262144LL,
         512, 0, 0, nullptr, dot, nullptr, nullptr, 0.125f};
    hmma_gemm<<<dim3(4, 2, 16), 256, SMEM_REQ>>>(q2_h, q2_l, k2_h, k2_l, p);

    // Stage 4: softmax + split
    softmax_split_kernel<<<8192, 256>>>(dot, attn_h, attn_l);

    // Stage 5 (transposed): outT[b][m][h*512+c] = v2T[z][m] . attn[z][c]
    p = {8, 512, 512, 3, 7,  32768, 4096, 0,  4096, 512, 0,  16777216LL, 512LL,
         4096, 0, 1, nullptr, nullptr, outT_h, outT_l, 1.0f};
    hmma_gemm<<<dim3(4, 16, 16), 256, SMEM_REQ>>>(v2T_h, v2T_l, attn_h, attn_l, p);

    // Stage 6: y[b] = Wout @ outT[b]^T + bout -> fp32 d_out
    p = {64, 4096, 4096, 0, 0,  0, 0, 0,  4096, 0, 0,  16777216LL, 0,
         4096, 1, 0, bout, y, nullptr, nullptr, 1.0f};
    hmma_gemm<<<dim3(32, 16, 2), 256, SMEM_REQ>>>(Wout_h, Wout_l, outT_h, outT_l, p);

    (void)in_sizes; (void)n_in; (void)out_size;
}

// round 11
// speedup vs baseline: 1.4116x; 1.3297x over previous
#include <cuda_runtime.h>
#include <cuda_bf16.h>
#include <cuda_fp16.h>
#include <cstdint>

// ============================================================================
// Mixed-precision HMMA pipeline. All GEMMs NT: D[m][n] = sum_k A[m][k]B[n][k].
//  - Pre-softmax path (stage1-q/k, 2q, 2k, logits): split-bf16 3-term
//    (AhBh + AhBl + AlBh), fp32 accum -> logit abs err ~1e-4.
//  - v-chain + post-softmax (stage1-v, 2v, attn@v, Wout): plain fp16 1-term.
// CTA tile 256x128x64, 8 warps (4Mx2N), 2-stage cp.async pipeline.
// ============================================================================

#define PADK 72                          // 64 data + 8 pad (144B rows)
#define A_TILE_ELT (256 * PADK)          // 18432
#define B_TILE_ELT (128 * PADK)          // 9216
#define STG_ELT (2 * A_TILE_ELT + 2 * B_TILE_ELT)   // bf16 3-term stage
#define STG_BYTES (STG_ELT * 2)          // 110592
#define SMEM_REQ (2 * STG_BYTES)         // 221184
#define OFF_AL (A_TILE_ELT * 2)
#define OFF_BH (2 * A_TILE_ELT * 2)
#define OFF_BL (2 * A_TILE_ELT * 2 + B_TILE_ELT * 2)

#define STG_ELT_H (A_TILE_ELT + B_TILE_ELT)         // fp16 1-term stage
#define STG_BYTES_H (STG_ELT_H * 2)      // 55296
#define SMEM_REQ_H (2 * STG_BYTES_H)     // 110592
#define OFF_BH_H (A_TILE_ELT * 2)

// ---- scratch (device globals) ----------------------------------------------
__device__ __align__(256) __nv_bfloat16 g_xT_hi[33554432],  g_xT_lo[33554432];
__device__ __align__(256) __half        g_xT_f[33554432];
__device__ __align__(256) __nv_bfloat16 g_Wqkv_hi[33554432],g_Wqkv_lo[33554432]; // qk rows
__device__ __align__(256) __half        g_Wqkv_vf[16777216];                     // v rows
__device__ __align__(256) __nv_bfloat16 g_Wq_hi[16777216],  g_Wq_lo[16777216];
__device__ __align__(256) __nv_bfloat16 g_Wk_hi[16777216],  g_Wk_lo[16777216];
__device__ __align__(256) __half        g_Wv_f[16777216],   g_Wout_f[16777216];
__device__ __align__(256) __nv_bfloat16 g_qkv_hi[67108864], g_qkv_lo[67108864];  // [2][8192][4096]
__device__ __align__(256) __half        g_v_f[33554432];                         // [2][4096][4096]
__device__ __align__(256) __nv_bfloat16 g_q2_hi[33554432],  g_q2_lo[33554432];
__device__ __align__(256) __nv_bfloat16 g_k2_hi[33554432],  g_k2_lo[33554432];
__device__ __align__(256) __half        g_v2T_f[33554432];
__device__ __align__(256) __half        g_attn_f[4194304];
__device__ __align__(256) __half        g_outT_f[33554432];
__device__ __align__(256) float g_dot[4194304];

// ---- helpers ----------------------------------------------------------------
__device__ __forceinline__ uint32_t smem_u32(const void* p) {
    uint32_t r;
    asm("{ .reg .u64 t; cvta.to.shared.u64 t, %1; cvt.u32.u64 %0, t; }" : "=r"(r) : "l"(p));
    return r;
}
__device__ __forceinline__ void cpasync16(uint32_t dst, const void* src) {
    asm volatile("cp.async.cg.shared.global [%0], [%1], 16;" :: "r"(dst), "l"(src));
}
__device__ __forceinline__ void mma16816(float* c, const uint32_t* a, const uint32_t* b) {
    asm volatile(
        "mma.sync.aligned.m16n8k16.row.col.f32.bf16.bf16.f32 "
        "{%0,%1,%2,%3}, {%4,%5,%6,%7}, {%8,%9}, {%0,%1,%2,%3};"
        : "+f"(c[0]), "+f"(c[1]), "+f"(c[2]), "+f"(c[3])
        : "r"(a[0]), "r"(a[1]), "r"(a[2]), "r"(a[3]), "r"(b[0]), "r"(b[1]));
}
__device__ __forceinline__ void mma16816h(float* c, const uint32_t* a, const uint32_t* b) {
    asm volatile(
        "mma.sync.aligned.m16n8k16.row.col.f32.f16.f16.f32 "
        "{%0,%1,%2,%3}, {%4,%5,%6,%7}, {%8,%9}, {%0,%1,%2,%3};"
        : "+f"(c[0]), "+f"(c[1]), "+f"(c[2]), "+f"(c[3])
        : "r"(a[0]), "r"(a[1]), "r"(a[2]), "r"(a[3]), "r"(b[0]), "r"(b[1]));
}
__device__ __forceinline__ void split2(float a, float b, uint32_t& hi, uint32_t& lo) {
    __nv_bfloat16 h0 = __float2bfloat16_rn(a), h1 = __float2bfloat16_rn(b);
    __nv_bfloat16 l0 = __float2bfloat16_rn(a - __bfloat162float(h0));
    __nv_bfloat16 l1 = __float2bfloat16_rn(b - __bfloat162float(h1));
    hi = (uint32_t)__bfloat16_as_ushort(h0) | ((uint32_t)__bfloat16_as_ushort(h1) << 16);
    lo = (uint32_t)__bfloat16_as_ushort(l0) | ((uint32_t)__bfloat16_as_ushort(l1) << 16);
}
__device__ __forceinline__ uint32_t packh2(float a, float b) {
    __half2 h = __floats2half2_rn(a, b);
    return *(uint32_t*)&h;
}

// ---- GEMM params --------------------------------------------------------------
struct GemmP {
    int nk, ldA, ldB, zshift, zmask;
    int aZ1, aZ2, aConst;
    int bZ1, bZ2, bConst;
    long long cZ1, cZ2;
    int ldC, biasMode, outMode;    // bias: 0 none 1 perM 2 perN; out: 0 f32 1 splitbf16 2 f16
    const float* bias;
    float* Cf;
    __nv_bfloat16* Chi; __nv_bfloat16* Clo;
    float alpha;
};

// ---- bf16 3-term GEMM (unchanged from best) -----------------------------------
__global__ void __launch_bounds__(256, 1)
hmma_gemm(const __nv_bfloat16* __restrict__ Ahg, const __nv_bfloat16* __restrict__ Alg,
          const __nv_bfloat16* __restrict__ Bhg, const __nv_bfloat16* __restrict__ Blg,
          const GemmP p)
{
    extern __shared__ __align__(16) __nv_bfloat16 sm[];
    const int tid = threadIdx.x, lane = tid & 31, wid = tid >> 5;
    const int wm = (wid >> 1) * 64, wn = (wid & 1) * 64;
    const int zh = blockIdx.z >> p.zshift, zl = blockIdx.z & p.zmask;
    const long long arow0 = (long long)p.aZ1 * zh + p.aZ2 * zl + p.aConst
                            + (long long)blockIdx.y * 256;
    const long long brow0 = (long long)p.bZ1 * zh + p.bZ2 * zl + p.bConst
                            + (long long)blockIdx.x * 128;
    const __nv_bfloat16* gAh = Ahg + arow0 * p.ldA;
    const __nv_bfloat16* gAl = Alg + arow0 * p.ldA;
    const __nv_bfloat16* gBh = Bhg + brow0 * p.ldB;
    const __nv_bfloat16* gBl = Blg + brow0 * p.ldB;
    const uint32_t smbase = smem_u32(sm);
    const int ldA = p.ldA, ldB = p.ldB, nk = p.nk;

    auto load_stage = [&](int st, int kb) {
        const uint32_t sb = smbase + (uint32_t)st * STG_BYTES;
        const long long koff = (long long)kb * 64;
#pragma unroll
        for (int i = 0; i < 8; i++) {
            const int c = tid + i * 256;
            const int row = c >> 3, ch = c & 7;
            const uint32_t doff = (uint32_t)(row * PADK + ch * 8) * 2;
            const long long ga = (long long)row * ldA + koff + ch * 8;
            cpasync16(sb + doff, gAh + ga);
            cpasync16(sb + OFF_AL + doff, gAl + ga);
        }
#pragma unroll
        for (int i = 0; i < 4; i++) {
            const int c = tid + i * 256;
            const int row = c >> 3, ch = c & 7;
            const uint32_t doff = (uint32_t)(row * PADK + ch * 8) * 2;
            const long long gb = (long long)row * ldB + koff + ch * 8;
            cpasync16(sb + OFF_BH + doff, gBh + gb);
            cpasync16(sb + OFF_BL + doff, gBl + gb);
        }
        asm volatile("cp.async.commit_group;" ::: "memory");
    };

    load_stage(0, 0);
    load_stage(1, 1);

    float acc[4][8][4];
#pragma unroll
    for (int a = 0; a < 4; a++)
#pragma unroll
        for (int b = 0; b < 8; b++)
#pragma unroll
            for (int c = 0; c < 4; c++) acc[a][b][c] = 0.0f;

    const int krow = (lane & 3) * 2;
    const int grow = lane >> 2;

    for (int kb = 0; kb < nk; kb++) {
        asm volatile("cp.async.wait_group 1;" ::: "memory");
        __syncthreads();
        const int st = kb & 1;
        const __nv_bfloat16* sAh = sm + (size_t)st * STG_ELT;
        const __nv_bfloat16* sAl = sAh + A_TILE_ELT;
        const __nv_bfloat16* sBh = sAl + A_TILE_ELT;
        const __nv_bfloat16* sBl = sBh + B_TILE_ELT;

#pragma unroll
        for (int k16 = 0; k16 < 4; k16++) {
            const int kk = k16 * 16 + krow;
            uint32_t ah[4][4], al[4][4];
#pragma unroll
            for (int mt = 0; mt < 4; mt++) {
                const int r0 = (wm + mt * 16 + grow) * PADK;
                const int r1 = r0 + 8 * PADK;
                ah[mt][0] = *(const uint32_t*)(sAh + r0 + kk);
                ah[mt][1] = *(const uint32_t*)(sAh + r1 + kk);
                ah[mt][2] = *(const uint32_t*)(sAh + r0 + kk + 8);
                ah[mt][3] = *(const uint32_t*)(sAh + r1 + kk + 8);
                al[mt][0] = *(const uint32_t*)(sAl + r0 + kk);
                al[mt][1] = *(const uint32_t*)(sAl + r1 + kk);
                al[mt][2] = *(const uint32_t*)(sAl + r0 + kk + 8);
                al[mt][3] = *(const uint32_t*)(sAl + r1 + kk + 8);
            }
#pragma unroll
            for (int nt = 0; nt < 8; nt++) {
                const int r = (wn + nt * 8 + grow) * PADK;
                uint32_t bh[2], bl[2];
                bh[0] = *(const uint32_t*)(sBh + r + kk);
                bh[1] = *(const uint32_t*)(sBh + r + kk + 8);
                bl[0] = *(const uint32_t*)(sBl + r + kk);
                bl[1] = *(const uint32_t*)(sBl + r + kk + 8);
#pragma unroll
                for (int mt = 0; mt < 4; mt++)
                    mma16816(acc[mt][nt], ah[mt], bh);
#pragma unroll
                for (int mt = 0; mt < 4; mt++)
                    mma16816(acc[mt][nt], ah[mt], bl);
#pragma unroll
                for (int mt = 0; mt < 4; mt++)
                    mma16816(acc[mt][nt], al[mt], bh);
            }
        }
        __syncthreads();
        if (kb + 2 < nk) load_stage(st, kb + 2);
    }

    const long long cbase = p.cZ1 * zh + p.cZ2 * zl;
    const int n0 = blockIdx.x * 128 + wn + (lane & 3) * 2;
    const int m0 = blockIdx.y * 256 + wm + (lane >> 2);
#pragma unroll
    for (int mt = 0; mt < 4; mt++) {
#pragma unroll
        for (int half = 0; half < 2; half++) {
            const int m = m0 + mt * 16 + half * 8;
            const float bm = (p.biasMode == 1) ? p.bias[m] : 0.0f;
            const long long rowoff = cbase + (long long)m * p.ldC;
#pragma unroll
            for (int nt = 0; nt < 8; nt++) {
                const int n = n0 + nt * 8;
                float v0 = acc[mt][nt][half * 2 + 0] * p.alpha + bm;
                float v1 = acc[mt][nt][half * 2 + 1] * p.alpha + bm;
                if (p.biasMode == 2) { v0 += p.bias[n]; v1 += p.bias[n + 1]; }
                if (p.outMode == 0) {
                    *(float2*)(p.Cf + rowoff + n) = make_float2(v0, v1);
                } else {
                    uint32_t h, l;
                    split2(v0, v1, h, l);
                    *(uint32_t*)(p.Chi + rowoff + n) = h;
                    *(uint32_t*)(p.Clo + rowoff + n) = l;
                }
            }
        }
    }
}

// ---- fp16 1-term GEMM ----------------------------------------------------------
__global__ void __launch_bounds__(256, 1)
hmma_gemm_f16(const __half* __restrict__ Ag, const __half* __restrict__ Bg,
              const GemmP p)
{
    extern __shared__ __align__(16) __half smh[];
    const int tid = threadIdx.x, lane = tid & 31, wid = tid >> 5;
    const int wm = (wid >> 1) * 64, wn = (wid & 1) * 64;
    const int zh = blockIdx.z >> p.zshift, zl = blockIdx.z & p.zmask;
    const long long arow0 = (long long)p.aZ1 * zh + p.aZ2 * zl + p.aConst
                            + (long long)blockIdx.y * 256;
    const long long brow0 = (long long)p.bZ1 * zh + p.bZ2 * zl + p.bConst
                            + (long long)blockIdx.x * 128;
    const __half* gA = Ag + arow0 * p.ldA;
    const __half* gB = Bg + brow0 * p.ldB;
    const uint32_t smbase = smem_u32(smh);
    const int ldA = p.ldA, ldB = p.ldB, nk = p.nk;

    auto load_stage = [&](int st, int kb) {
        const uint32_t sb = smbase + (uint32_t)st * STG_BYTES_H;
        const long long koff = (long long)kb * 64;
#pragma unroll
        for (int i = 0; i < 8; i++) {
            const int c = tid + i * 256;
            const int row = c >> 3, ch = c & 7;
            const uint32_t doff = (uint32_t)(row * PADK + ch * 8) * 2;
            cpasync16(sb + doff, gA + (long long)row * ldA + koff + ch * 8);
        }
#pragma unroll
        for (int i = 0; i < 4; i++) {
            const int c = tid + i * 256;
            const int row = c >> 3, ch = c & 7;
            const uint32_t doff = (uint32_t)(row * PADK + ch * 8) * 2;
            cpasync16(sb + OFF_BH_H + doff, gB + (long long)row * ldB + koff + ch * 8);
        }
        asm volatile("cp.async.commit_group;" ::: "memory");
    };

    load_stage(0, 0);
    load_stage(1, 1);

    float acc[4][8][4];
#pragma unroll
    for (int a = 0; a < 4; a++)
#pragma unroll
        for (int b = 0; b < 8; b++)
#pragma unroll
            for (int c = 0; c < 4; c++) acc[a][b][c] = 0.0f;

    const int krow = (lane & 3) * 2;
    const int grow = lane >> 2;

    for (int kb = 0; kb < nk; kb++) {
        asm volatile("cp.async.wait_group 1;" ::: "memory");
        __syncthreads();
        const int st = kb & 1;
        const __half* sA = smh + (size_t)st * STG_ELT_H;
        const __half* sB = sA + A_TILE_ELT;

#pragma unroll
        for (int k16 = 0; k16 < 4; k16++) {
            const int kk = k16 * 16 + krow;
            uint32_t ah[4][4];
#pragma unroll
            for (int mt = 0; mt < 4; mt++) {
                const int r0 = (wm + mt * 16 + grow) * PADK;
                const int r1 = r0 + 8 * PADK;
                ah[mt][0] = *(const uint32_t*)(sA + r0 + kk);
                ah[mt][1] = *(const uint32_t*)(sA + r1 + kk);
                ah[mt][2] = *(const uint32_t*)(sA + r0 + kk + 8);
                ah[mt][3] = *(const uint32_t*)(sA + r1 + kk + 8);
            }
#pragma unroll
            for (int nt = 0; nt < 8; nt++) {
                const int r = (wn + nt * 8 + grow) * PADK;
                uint32_t bh[2];
                bh[0] = *(const uint32_t*)(sB + r + kk);
                bh[1] = *(const uint32_t*)(sB + r + kk + 8);
#pragma unroll
                for (int mt = 0; mt < 4; mt++)
                    mma16816h(acc[mt][nt], ah[mt], bh);
            }
        }
        __syncthreads();
        if (kb + 2 < nk) load_stage(st, kb + 2);
    }

    const long long cbase = p.cZ1 * zh + p.cZ2 * zl;
    const int n0 = blockIdx.x * 128 + wn + (lane & 3) * 2;
    const int m0 = blockIdx.y * 256 + wm + (lane >> 2);
    __half* Ch = (__half*)p.Chi;
#pragma unroll
    for (int mt = 0; mt < 4; mt++) {
#pragma unroll
        for (int half = 0; half < 2; half++) {
            const int m = m0 + mt * 16 + half * 8;
            const float bm = (p.biasMode == 1) ? p.bias[m] : 0.0f;
            const long long rowoff = cbase + (long long)m * p.ldC;
#pragma unroll
            for (int nt = 0; nt < 8; nt++) {
                const int n = n0 + nt * 8;
                float v0 = acc[mt][nt][half * 2 + 0] * p.alpha + bm;
                float v1 = acc[mt][nt][half * 2 + 1] * p.alpha + bm;
                if (p.biasMode == 2) { v0 += p.bias[n]; v1 += p.bias[n + 1]; }
                if (p.outMode == 0) {
                    *(float2*)(p.Cf + rowoff + n) = make_float2(v0, v1);
                } else {
                    *(uint32_t*)(Ch + rowoff + n) = packh2(v0, v1);
                }
            }
        }
    }
}

// ---- conversions -------------------------------------------------------------
__global__ void split_kernel(const float4* __restrict__ in, uint2* __restrict__ hi,
                             uint2* __restrict__ lo, int n4)
{
    int i = blockIdx.x * 256 + threadIdx.x;
    if (i >= n4) return;
    float4 v = in[i];
    uint32_t h0, l0, h1, l1;
    split2(v.x, v.y, h0, l0);
    split2(v.z, v.w, h1, l1);
    hi[i] = make_uint2(h0, h1);
    lo[i] = make_uint2(l0, l1);
}

__global__ void half_kernel(const float4* __restrict__ in, uint2* __restrict__ out,
                            int n4)
{
    int i = blockIdx.x * 256 + threadIdx.x;
    if (i >= n4) return;
    float4 v = in[i];
    out[i] = make_uint2(packh2(v.x, v.y), packh2(v.z, v.w));
}

// x[b][c][n] fp32 -> xT[b][n][c] split bf16 + fp16 (4096x4096 per batch)
__global__ void transpose_split_kernel(const float* __restrict__ x,
                                       __nv_bfloat16* __restrict__ hi,
                                       __nv_bfloat16* __restrict__ lo,
                                       __half* __restrict__ hf)
{
    __shared__ float tile[32][33];
    const int b = blockIdx.z;
    const int c0 = blockIdx.y * 32, n0 = blockIdx.x * 32;
    const int tx = threadIdx.x, ty = threadIdx.y;
    const float* xb = x + (long long)b * 16777216;
#pragma unroll
    for (int i = 0; i < 4; i++)
        tile[ty + i * 8][tx] = xb[(long long)(c0 + ty + i * 8) * 4096 + n0 + tx];
    __syncthreads();
#pragma unroll
    for (int i = 0; i < 4; i++) {
        float v = tile[tx][ty + i * 8];
        __nv_bfloat16 h = __float2bfloat16_rn(v);
        __nv_bfloat16 l = __float2bfloat16_rn(v - __bfloat162float(h));
        long long o = (long long)b * 16777216 + (long long)(n0 + ty + i * 8) * 4096 + c0 + tx;
        hi[o] = h; lo[o] = l; hf[o] = __float2half_rn(v);
    }
}

// softmax over rows of 512, output fp16
__global__ void softmax_f16_kernel(const float* __restrict__ dot,
                                   __half* __restrict__ attn)
{
    const long long row = blockIdx.x;
    const float* p = dot + row * 512;
    __shared__ float red[256];
    const int t = threadIdx.x;
    float v0 = p[t], v1 = p[t + 256];
    red[t] = fmaxf(v0, v1); __syncthreads();
#pragma unroll
    for (int s = 128; s > 0; s >>= 1) {
        if (t < s) red[t] = fmaxf(red[t], red[t + s]);
        __syncthreads();
    }
    float mx = red[0]; __syncthreads();
    float e0 = expf(v0 - mx), e1 = expf(v1 - mx);
    red[t] = e0 + e1; __syncthreads();
#pragma unroll
    for (int s = 128; s > 0; s >>= 1) {
        if (t < s) red[t] += red[t + s];
        __syncthreads();
    }
    float inv = 1.0f / red[0];
    attn[row * 512 + t]       = __float2half_rn(e0 * inv);
    attn[row * 512 + t + 256] = __float2half_rn(e1 * inv);
}

// ---- host --------------------------------------------------------------------
extern "C" void kernel_launch(void* const* d_in, const int* in_sizes, int n_in,
                              void* d_out, int out_size)
{
    const float* x    = (const float*)d_in[0];
    const float* Wqkv = (const float*)d_in[1];
    const float* bqkv = (const float*)d_in[2];
    const float* Wq   = (const float*)d_in[3];
    const float* bq   = (const float*)d_in[4];
    const float* Wk   = (const float*)d_in[5];
    const float* bk   = (const float*)d_in[6];
    const float* Wv   = (const float*)d_in[7];
    const float* bv   = (const float*)d_in[8];
    const float* Wout = (const float*)d_in[9];
    const float* bout = (const float*)d_in[10];
    float* y = (float*)d_out;

    __nv_bfloat16 *xT_h, *xT_l, *Wqkv_h, *Wqkv_l, *Wq_h, *Wq_l, *Wk_h, *Wk_l,
        *qkv_h, *qkv_l, *q2_h, *q2_l, *k2_h, *k2_l;
    __half *xT_f, *Wqkv_vf, *Wv_f, *Wout_f, *v_f, *v2T_f, *attn_f, *outT_f;
    float* dot;
    cudaGetSymbolAddress((void**)&xT_h,   g_xT_hi);   cudaGetSymbolAddress((void**)&xT_l,   g_xT_lo);
    cudaGetSymbolAddress((void**)&xT_f,   g_xT_f);
    cudaGetSymbolAddress((void**)&Wqkv_h, g_Wqkv_hi); cudaGetSymbolAddress((void**)&Wqkv_l, g_Wqkv_lo);
    cudaGetSymbolAddress((void**)&Wqkv_vf,g_Wqkv_vf);
    cudaGetSymbolAddress((void**)&Wq_h,   g_Wq_hi);   cudaGetSymbolAddress((void**)&Wq_l,   g_Wq_lo);
    cudaGetSymbolAddress((void**)&Wk_h,   g_Wk_hi);   cudaGetSymbolAddress((void**)&Wk_l,   g_Wk_lo);
    cudaGetSymbolAddress((void**)&Wv_f,   g_Wv_f);    cudaGetSymbolAddress((void**)&Wout_f, g_Wout_f);
    cudaGetSymbolAddress((void**)&qkv_h,  g_qkv_hi);  cudaGetSymbolAddress((void**)&qkv_l,  g_qkv_lo);
    cudaGetSymbolAddress((void**)&v_f,    g_v_f);
    cudaGetSymbolAddress((void**)&q2_h,   g_q2_hi);   cudaGetSymbolAddress((void**)&q2_l,   g_q2_lo);
    cudaGetSymbolAddress((void**)&k2_h,   g_k2_hi);   cudaGetSymbolAddress((void**)&k2_l,   g_k2_lo);
    cudaGetSymbolAddress((void**)&v2T_f,  g_v2T_f);
    cudaGetSymbolAddress((void**)&attn_f, g_attn_f);
    cudaGetSymbolAddress((void**)&outT_f, g_outT_f);
    cudaGetSymbolAddress((void**)&dot,    g_dot);

    cudaFuncSetAttribute(hmma_gemm, cudaFuncAttributeMaxDynamicSharedMemorySize, SMEM_REQ);
    cudaFuncSetAttribute(hmma_gemm_f16, cudaFuncAttributeMaxDynamicSharedMemorySize, SMEM_REQ_H);

    // conversions (launch order: hmma stage1qk is the 6th launch -> ncu -s 5 -c 1)
    transpose_split_kernel<<<dim3(128, 128, 2), dim3(32, 8)>>>(x, xT_h, xT_l, xT_f);
    split_kernel<<<32768, 256>>>((const float4*)Wqkv, (uint2*)Wqkv_h, (uint2*)Wqkv_l, 8388608);
    split_kernel<<<16384, 256>>>((const float4*)Wq, (uint2*)Wq_h, (uint2*)Wq_l, 4194304);
    split_kernel<<<16384, 256>>>((const float4*)Wk, (uint2*)Wk_h, (uint2*)Wk_l, 4194304);
    half_kernel<<<16384, 256>>>((const float4*)(Wqkv + 33554432LL), (uint2*)Wqkv_vf, 4194304);

    GemmP p;
    // Stage 1qk: qkv_qk[b] = Wqkv[0:8192] @ xT[b]^T + bqkv -> split [2][8192][4096]
    p = {64, 4096, 4096, 0, 0,  0, 0, 0,  4096, 0, 0,  33554432LL, 0,
         4096, 1, 1, bqkv, nullptr, qkv_h, qkv_l, 1.0f};
    hmma_gemm<<<dim3(32, 32, 2), 256, SMEM_REQ>>>(Wqkv_h, Wqkv_l, xT_h, xT_l, p);

    half_kernel<<<16384, 256>>>((const float4*)Wv,   (uint2*)Wv_f,   4194304);
    half_kernel<<<16384, 256>>>((const float4*)Wout, (uint2*)Wout_f, 4194304);

    // Stage 1v (fp16): v[b] = Wqkv_v @ xT[b]^T + bqkv_v -> fp16 [2][4096][4096]
    p = {64, 4096, 4096, 0, 0,  0, 0, 0,  4096, 0, 0,  16777216LL, 0,
         4096, 1, 2, bqkv + 8192, nullptr, (__nv_bfloat16*)v_f, nullptr, 1.0f};
    hmma_gemm_f16<<<dim3(32, 16, 2), 256, SMEM_REQ_H>>>(Wqkv_vf, xT_f, p);

    // Stage 2q: q2[z] = qkv_q[z] @ Wq^T + bq   (z = b*8+h)
    p = {64, 4096, 4096, 3, 7,  8192, 512, 0,  0, 0, 0,  16777216LL, 2097152LL,
         4096, 2, 1, bq, nullptr, q2_h, q2_l, 1.0f};
    hmma_gemm<<<dim3(32, 2, 16), 256, SMEM_REQ>>>(qkv_h, qkv_l, Wq_h, Wq_l, p);
    // Stage 2k
    p = {64, 4096, 4096, 3, 7,  8192, 512, 4096,  0, 0, 0,  16777216LL, 2097152LL,
         4096, 2, 1, bk, nullptr, k2_h, k2_l, 1.0f};
    hmma_gemm<<<dim3(32, 2, 16), 256, SMEM_REQ>>>(qkv_h, qkv_l, Wk_h, Wk_l, p);
    // Stage 2v (fp16, transposed): v2T[b][h][m][d] = Wv[m] . v[z][d] + bv[m]
    p = {64, 4096, 4096, 3, 7,  0, 0, 0,  4096, 512, 0,  16777216LL, 2097152LL,
         512, 1, 2, bv, nullptr, (__nv_bfloat16*)v2T_f, nullptr, 1.0f};
    hmma_gemm_f16<<<dim3(4, 16, 16), 256, SMEM_REQ_H>>>(Wv_f, v_f, p);

    // Stage 3: dot[z] = q2[z] @ k2[z]^T * 0.125 -> fp32
    p = {64, 4096, 4096, 3, 7,  4096, 512, 0,  4096, 512, 0,  2097152LL, 262144LL,
         512, 0, 0, nullptr, dot, nullptr, nullptr, 0.125f};
    hmma_gemm<<<dim3(4, 2, 16), 256, SMEM_REQ>>>(q2_h, q2_l, k2_h, k2_l, p);

    // Stage 4: softmax -> fp16
    softmax_f16_kernel<<<8192, 256>>>(dot, attn_f);

    // Stage 5 (fp16, transposed): outT[b][m][h*512+c] = v2T[z][m] . attn[z][c]
    p = {8, 512, 512, 3, 7,  32768, 4096, 0,  4096, 512, 0,  16777216LL, 512LL,
         4096, 0, 2, nullptr, nullptr, (__nv_bfloat16*)outT_f, nullptr, 1.0f};
    hmma_gemm_f16<<<dim3(4, 16, 16), 256, SMEM_REQ_H>>>(v2T_f, attn_f, p);

    // Stage 6 (fp16): y[b] = Wout @ outT[b]^T + bout -> fp32 d_out
    p = {64, 4096, 4096, 0, 0,  0, 0, 0,  4096, 0, 0,  16777216LL, 0,
         4096, 1, 0, bout, y, nullptr, nullptr, 1.0f};
    hmma_gemm_f16<<<dim3(32, 16, 2), 256, SMEM_REQ_H>>>(Wout_f, outT_f, p);

    (void)in_sizes; (void)n_in; (void)out_size;
}

// round 12
// speedup vs baseline: 1.4847x; 1.0518x over previous
#include <cuda_runtime.h>
#include <cuda_bf16.h>
#include <cuda_fp16.h>
#include <cstdint>

// ============================================================================
// Mixed-precision HMMA pipeline. All GEMMs NT: D[m][n] = sum_k A[m][k]B[n][k].
//  - Pre-softmax path: split-bf16 3-term (AhBh + AhBl + AlBh), fp32 accum.
//  - v-chain + post-softmax: plain fp16 1-term.
// Logit path restructured via associativity (softmax row-const cancellation):
//   logits ~ 0.125*(qkv_q . H . qkv_k^T)[c,d] + 0.125*beta[d]
//   H[n'][n] = sum_m Wk[m,n'] Wq[m,n]   (computed ONCE)
//   beta[d]  = sum_n w[n] qkv_k[d,n],  w = Wk^T bq
// This removes the per-(b,h) k-projection GEMM entirely.
// ============================================================================

#define PADK 72
#define A_TILE_ELT (256 * PADK)
#define B_TILE_ELT (128 * PADK)
#define STG_ELT (2 * A_TILE_ELT + 2 * B_TILE_ELT)
#define STG_BYTES (STG_ELT * 2)
#define SMEM_REQ (2 * STG_BYTES)
#define OFF_AL (A_TILE_ELT * 2)
#define OFF_BH (2 * A_TILE_ELT * 2)
#define OFF_BL (2 * A_TILE_ELT * 2 + B_TILE_ELT * 2)

#define STG_ELT_H (A_TILE_ELT + B_TILE_ELT)
#define STG_BYTES_H (STG_ELT_H * 2)
#define SMEM_REQ_H (2 * STG_BYTES_H)
#define OFF_BH_H (A_TILE_ELT * 2)

// ---- scratch (device globals) ----------------------------------------------
__device__ __align__(256) __nv_bfloat16 g_xT_hi[33554432],  g_xT_lo[33554432];
__device__ __align__(256) __half        g_xT_f[33554432];
__device__ __align__(256) __nv_bfloat16 g_Wqkv_hi[33554432],g_Wqkv_lo[33554432];
__device__ __align__(256) __half        g_Wqkv_vf[16777216];
__device__ __align__(256) __nv_bfloat16 g_WqT_hi[16777216], g_WqT_lo[16777216];
__device__ __align__(256) __nv_bfloat16 g_WkT_hi[16777216], g_WkT_lo[16777216];
__device__ __align__(256) __half        g_Wv_f[16777216],   g_Wout_f[16777216];
__device__ __align__(256) __nv_bfloat16 g_qkv_hi[67108864], g_qkv_lo[67108864];
__device__ __align__(256) __half        g_v_f[33554432];
__device__ __align__(256) __nv_bfloat16 g_q2_hi[33554432],  g_q2_lo[33554432];
__device__ __align__(256) __nv_bfloat16 g_H_hi[16777216],   g_H_lo[16777216];
__device__ __align__(256) __half        g_v2T_f[33554432];
__device__ __align__(256) __half        g_attn_f[4194304];
__device__ __align__(256) __half        g_outT_f[33554432];
__device__ __align__(256) float g_dot[4194304];
__device__ __align__(256) float g_wvec[4096];
__device__ __align__(256) float g_beta[8192];

// ---- helpers ----------------------------------------------------------------
__device__ __forceinline__ uint32_t smem_u32(const void* p) {
    uint32_t r;
    asm("{ .reg .u64 t; cvta.to.shared.u64 t, %1; cvt.u32.u64 %0, t; }" : "=r"(r) : "l"(p));
    return r;
}
__device__ __forceinline__ void cpasync16(uint32_t dst, const void* src) {
    asm volatile("cp.async.cg.shared.global [%0], [%1], 16;" :: "r"(dst), "l"(src));
}
__device__ __forceinline__ void mma16816(float* c, const uint32_t* a, const uint32_t* b) {
    asm volatile(
        "mma.sync.aligned.m16n8k16.row.col.f32.bf16.bf16.f32 "
        "{%0,%1,%2,%3}, {%4,%5,%6,%7}, {%8,%9}, {%0,%1,%2,%3};"
        : "+f"(c[0]), "+f"(c[1]), "+f"(c[2]), "+f"(c[3])
        : "r"(a[0]), "r"(a[1]), "r"(a[2]), "r"(a[3]), "r"(b[0]), "r"(b[1]));
}
__device__ __forceinline__ void mma16816h(float* c, const uint32_t* a, const uint32_t* b) {
    asm volatile(
        "mma.sync.aligned.m16n8k16.row.col.f32.f16.f16.f32 "
        "{%0,%1,%2,%3}, {%4,%5,%6,%7}, {%8,%9}, {%0,%1,%2,%3};"
        : "+f"(c[0]), "+f"(c[1]), "+f"(c[2]), "+f"(c[3])
        : "r"(a[0]), "r"(a[1]), "r"(a[2]), "r"(a[3]), "r"(b[0]), "r"(b[1]));
}
__device__ __forceinline__ void split2(float a, float b, uint32_t& hi, uint32_t& lo) {
    __nv_bfloat16 h0 = __float2bfloat16_rn(a), h1 = __float2bfloat16_rn(b);
    __nv_bfloat16 l0 = __float2bfloat16_rn(a - __bfloat162float(h0));
    __nv_bfloat16 l1 = __float2bfloat16_rn(b - __bfloat162float(h1));
    hi = (uint32_t)__bfloat16_as_ushort(h0) | ((uint32_t)__bfloat16_as_ushort(h1) << 16);
    lo = (uint32_t)__bfloat16_as_ushort(l0) | ((uint32_t)__bfloat16_as_ushort(l1) << 16);
}
__device__ __forceinline__ uint32_t packh2(float a, float b) {
    __half2 h = __floats2half2_rn(a, b);
    return *(uint32_t*)&h;
}

// ---- GEMM params --------------------------------------------------------------
struct GemmP {
    int nk, ldA, ldB, zshift, zmask;
    int aZ1, aZ2, aConst;
    int bZ1, bZ2, bConst;
    long long cZ1, cZ2;
    int ldC, biasMode, outMode;
    const float* bias;
    float* Cf;
    __nv_bfloat16* Chi; __nv_bfloat16* Clo;
    float alpha;
};

// ---- bf16 3-term GEMM ----------------------------------------------------------
__global__ void __launch_bounds__(256, 1)
hmma_gemm(const __nv_bfloat16* __restrict__ Ahg, const __nv_bfloat16* __restrict__ Alg,
          const __nv_bfloat16* __restrict__ Bhg, const __nv_bfloat16* __restrict__ Blg,
          const GemmP p)
{
    extern __shared__ __align__(16) __nv_bfloat16 sm[];
    const int tid = threadIdx.x, lane = tid & 31, wid = tid >> 5;
    const int wm = (wid >> 1) * 64, wn = (wid & 1) * 64;
    const int zh = blockIdx.z >> p.zshift, zl = blockIdx.z & p.zmask;
    const long long arow0 = (long long)p.aZ1 * zh + p.aZ2 * zl + p.aConst
                            + (long long)blockIdx.y * 256;
    const long long brow0 = (long long)p.bZ1 * zh + p.bZ2 * zl + p.bConst
                            + (long long)blockIdx.x * 128;
    const __nv_bfloat16* gAh = Ahg + arow0 * p.ldA;
    const __nv_bfloat16* gAl = Alg + arow0 * p.ldA;
    const __nv_bfloat16* gBh = Bhg + brow0 * p.ldB;
    const __nv_bfloat16* gBl = Blg + brow0 * p.ldB;
    const uint32_t smbase = smem_u32(sm);
    const int ldA = p.ldA, ldB = p.ldB, nk = p.nk;

    auto load_stage = [&](int st, int kb) {
        const uint32_t sb = smbase + (uint32_t)st * STG_BYTES;
        const long long koff = (long long)kb * 64;
#pragma unroll
        for (int i = 0; i < 8; i++) {
            const int c = tid + i * 256;
            const int row = c >> 3, ch = c & 7;
            const uint32_t doff = (uint32_t)(row * PADK + ch * 8) * 2;
            const long long ga = (long long)row * ldA + koff + ch * 8;
            cpasync16(sb + doff, gAh + ga);
            cpasync16(sb + OFF_AL + doff, gAl + ga);
        }
#pragma unroll
        for (int i = 0; i < 4; i++) {
            const int c = tid + i * 256;
            const int row = c >> 3, ch = c & 7;
            const uint32_t doff = (uint32_t)(row * PADK + ch * 8) * 2;
            const long long gb = (long long)row * ldB + koff + ch * 8;
            cpasync16(sb + OFF_BH + doff, gBh + gb);
            cpasync16(sb + OFF_BL + doff, gBl + gb);
        }
        asm volatile("cp.async.commit_group;" ::: "memory");
    };

    load_stage(0, 0);
    load_stage(1, 1);

    float acc[4][8][4];
#pragma unroll
    for (int a = 0; a < 4; a++)
#pragma unroll
        for (int b = 0; b < 8; b++)
#pragma unroll
            for (int c = 0; c < 4; c++) acc[a][b][c] = 0.0f;

    const int krow = (lane & 3) * 2;
    const int grow = lane >> 2;

    for (int kb = 0; kb < nk; kb++) {
        asm volatile("cp.async.wait_group 1;" ::: "memory");
        __syncthreads();
        const int st = kb & 1;
        const __nv_bfloat16* sAh = sm + (size_t)st * STG_ELT;
        const __nv_bfloat16* sAl = sAh + A_TILE_ELT;
        const __nv_bfloat16* sBh = sAl + A_TILE_ELT;
        const __nv_bfloat16* sBl = sBh + B_TILE_ELT;

#pragma unroll
        for (int k16 = 0; k16 < 4; k16++) {
            const int kk = k16 * 16 + krow;
            uint32_t ah[4][4], al[4][4];
#pragma unroll
            for (int mt = 0; mt < 4; mt++) {
                const int r0 = (wm + mt * 16 + grow) * PADK;
                const int r1 = r0 + 8 * PADK;
                ah[mt][0] = *(const uint32_t*)(sAh + r0 + kk);
                ah[mt][1] = *(const uint32_t*)(sAh + r1 + kk);
                ah[mt][2] = *(const uint32_t*)(sAh + r0 + kk + 8);
                ah[mt][3] = *(const uint32_t*)(sAh + r1 + kk + 8);
                al[mt][0] = *(const uint32_t*)(sAl + r0 + kk);
                al[mt][1] = *(const uint32_t*)(sAl + r1 + kk);
                al[mt][2] = *(const uint32_t*)(sAl + r0 + kk + 8);
                al[mt][3] = *(const uint32_t*)(sAl + r1 + kk + 8);
            }
#pragma unroll
            for (int nt = 0; nt < 8; nt++) {
                const int r = (wn + nt * 8 + grow) * PADK;
                uint32_t bh[2], bl[2];
                bh[0] = *(const uint32_t*)(sBh + r + kk);
                bh[1] = *(const uint32_t*)(sBh + r + kk + 8);
                bl[0] = *(const uint32_t*)(sBl + r + kk);
                bl[1] = *(const uint32_t*)(sBl + r + kk + 8);
#pragma unroll
                for (int mt = 0; mt < 4; mt++)
                    mma16816(acc[mt][nt], ah[mt], bh);
#pragma unroll
                for (int mt = 0; mt < 4; mt++)
                    mma16816(acc[mt][nt], ah[mt], bl);
#pragma unroll
                for (int mt = 0; mt < 4; mt++)
                    mma16816(acc[mt][nt], al[mt], bh);
            }
        }
        __syncthreads();
        if (kb + 2 < nk) load_stage(st, kb + 2);
    }

    const long long cbase = p.cZ1 * zh + p.cZ2 * zl;
    const int n0 = blockIdx.x * 128 + wn + (lane & 3) * 2;
    const int m0 = blockIdx.y * 256 + wm + (lane >> 2);
#pragma unroll
    for (int mt = 0; mt < 4; mt++) {
#pragma unroll
        for (int half = 0; half < 2; half++) {
            const int m = m0 + mt * 16 + half * 8;
            const float bm = (p.biasMode == 1) ? p.bias[m] : 0.0f;
            const long long rowoff = cbase + (long long)m * p.ldC;
#pragma unroll
            for (int nt = 0; nt < 8; nt++) {
                const int n = n0 + nt * 8;
                float v0 = acc[mt][nt][half * 2 + 0] * p.alpha + bm;
                float v1 = acc[mt][nt][half * 2 + 1] * p.alpha + bm;
                if (p.biasMode == 2) { v0 += p.bias[n]; v1 += p.bias[n + 1]; }
                if (p.outMode == 0) {
                    *(float2*)(p.Cf + rowoff + n) = make_float2(v0, v1);
                } else {
                    uint32_t h, l;
                    split2(v0, v1, h, l);
                    *(uint32_t*)(p.Chi + rowoff + n) = h;
                    *(uint32_t*)(p.Clo + rowoff + n) = l;
                }
            }
        }
    }
}

// ---- fp16 1-term GEMM ----------------------------------------------------------
__global__ void __launch_bounds__(256, 1)
hmma_gemm_f16(const __half* __restrict__ Ag, const __half* __restrict__ Bg,
              const GemmP p)
{
    extern __shared__ __align__(16) __half smh[];
    const int tid = threadIdx.x, lane = tid & 31, wid = tid >> 5;
    const int wm = (wid >> 1) * 64, wn = (wid & 1) * 64;
    const int zh = blockIdx.z >> p.zshift, zl = blockIdx.z & p.zmask;
    const long long arow0 = (long long)p.aZ1 * zh + p.aZ2 * zl + p.aConst
                            + (long long)blockIdx.y * 256;
    const long long brow0 = (long long)p.bZ1 * zh + p.bZ2 * zl + p.bConst
                            + (long long)blockIdx.x * 128;
    const __half* gA = Ag + arow0 * p.ldA;
    const __half* gB = Bg + brow0 * p.ldB;
    const uint32_t smbase = smem_u32(smh);
    const int ldA = p.ldA, ldB = p.ldB, nk = p.nk;

    auto load_stage = [&](int st, int kb) {
        const uint32_t sb = smbase + (uint32_t)st * STG_BYTES_H;
        const long long koff = (long long)kb * 64;
#pragma unroll
        for (int i = 0; i < 8; i++) {
            const int c = tid + i * 256;
            const int row = c >> 3, ch = c & 7;
            const uint32_t doff = (uint32_t)(row * PADK + ch * 8) * 2;
            cpasync16(sb + doff, gA + (long long)row * ldA + koff + ch * 8);
        }
#pragma unroll
        for (int i = 0; i < 4; i++) {
            const int c = tid + i * 256;
            const int row = c >> 3, ch = c & 7;
            const uint32_t doff = (uint32_t)(row * PADK + ch * 8) * 2;
            cpasync16(sb + OFF_BH_H + doff, gB + (long long)row * ldB + koff + ch * 8);
        }
        asm volatile("cp.async.commit_group;" ::: "memory");
    };

    load_stage(0, 0);
    load_stage(1, 1);

    float acc[4][8][4];
#pragma unroll
    for (int a = 0; a < 4; a++)
#pragma unroll
        for (int b = 0; b < 8; b++)
#pragma unroll
            for (int c = 0; c < 4; c++) acc[a][b][c] = 0.0f;

    const int krow = (lane & 3) * 2;
    const int grow = lane >> 2;

    for (int kb = 0; kb < nk; kb++) {
        asm volatile("cp.async.wait_group 1;" ::: "memory");
        __syncthreads();
        const int st = kb & 1;
        const __half* sA = smh + (size_t)st * STG_ELT_H;
        const __half* sB = sA + A_TILE_ELT;

#pragma unroll
        for (int k16 = 0; k16 < 4; k16++) {
            const int kk = k16 * 16 + krow;
            uint32_t ah[4][4];
#pragma unroll
            for (int mt = 0; mt < 4; mt++) {
                const int r0 = (wm + mt * 16 + grow) * PADK;
                const int r1 = r0 + 8 * PADK;
                ah[mt][0] = *(const uint32_t*)(sA + r0 + kk);
                ah[mt][1] = *(const uint32_t*)(sA + r1 + kk);
                ah[mt][2] = *(const uint32_t*)(sA + r0 + kk + 8);
                ah[mt][3] = *(const uint32_t*)(sA + r1 + kk + 8);
            }
#pragma unroll
            for (int nt = 0; nt < 8; nt++) {
                const int r = (wn + nt * 8 + grow) * PADK;
                uint32_t bh[2];
                bh[0] = *(const uint32_t*)(sB + r + kk);
                bh[1] = *(const uint32_t*)(sB + r + kk + 8);
#pragma unroll
                for (int mt = 0; mt < 4; mt++)
                    mma16816h(acc[mt][nt], ah[mt], bh);
            }
        }
        __syncthreads();
        if (kb + 2 < nk) load_stage(st, kb + 2);
    }

    const long long cbase = p.cZ1 * zh + p.cZ2 * zl;
    const int n0 = blockIdx.x * 128 + wn + (lane & 3) * 2;
    const int m0 = blockIdx.y * 256 + wm + (lane >> 2);
    __half* Ch = (__half*)p.Chi;
#pragma unroll
    for (int mt = 0; mt < 4; mt++) {
#pragma unroll
        for (int half = 0; half < 2; half++) {
            const int m = m0 + mt * 16 + half * 8;
            const float bm = (p.biasMode == 1) ? p.bias[m] : 0.0f;
            const long long rowoff = cbase + (long long)m * p.ldC;
#pragma unroll
            for (int nt = 0; nt < 8; nt++) {
                const int n = n0 + nt * 8;
                float v0 = acc[mt][nt][half * 2 + 0] * p.alpha + bm;
                float v1 = acc[mt][nt][half * 2 + 1] * p.alpha + bm;
                if (p.biasMode == 2) { v0 += p.bias[n]; v1 += p.bias[n + 1]; }
                if (p.outMode == 0) {
                    *(float2*)(p.Cf + rowoff + n) = make_float2(v0, v1);
                } else {
                    *(uint32_t*)(Ch + rowoff + n) = packh2(v0, v1);
                }
            }
        }
    }
}

// ---- conversions -------------------------------------------------------------
__global__ void split_kernel(const float4* __restrict__ in, uint2* __restrict__ hi,
                             uint2* __restrict__ lo, int n4)
{
    int i = blockIdx.x * 256 + threadIdx.x;
    if (i >= n4) return;
    float4 v = in[i];
    uint32_t h0, l0, h1, l1;
    split2(v.x, v.y, h0, l0);
    split2(v.z, v.w, h1, l1);
    hi[i] = make_uint2(h0, h1);
    lo[i] = make_uint2(l0, l1);
}

__global__ void half_kernel(const float4* __restrict__ in, uint2* __restrict__ out,
                            int n4)
{
    int i = blockIdx.x * 256 + threadIdx.x;
    if (i >= n4) return;
    float4 v = in[i];
    out[i] = make_uint2(packh2(v.x, v.y), packh2(v.z, v.w));
}

// x[b][c][n] fp32 -> xT[b][n][c] split bf16 + fp16 (4096x4096 per batch)
__global__ void transpose_split_kernel(const float* __restrict__ x,
                                       __nv_bfloat16* __restrict__ hi,
                                       __nv_bfloat16* __restrict__ lo,
                                       __half* __restrict__ hf)
{
    __shared__ float tile[32][33];
    const int b = blockIdx.z;
    const int c0 = blockIdx.y * 32, n0 = blockIdx.x * 32;
    const int tx = threadIdx.x, ty = threadIdx.y;
    const float* xb = x + (long long)b * 16777216;
#pragma unroll
    for (int i = 0; i < 4; i++)
        tile[ty + i * 8][tx] = xb[(long long)(c0 + ty + i * 8) * 4096 + n0 + tx];
    __syncthreads();
#pragma unroll
    for (int i = 0; i < 4; i++) {
        float v = tile[tx][ty + i * 8];
        __nv_bfloat16 h = __float2bfloat16_rn(v);
        __nv_bfloat16 l = __float2bfloat16_rn(v - __bfloat162float(h));
        long long o = (long long)b * 16777216 + (long long)(n0 + ty + i * 8) * 4096 + c0 + tx;
        hi[o] = h; lo[o] = l; hf[o] = __float2half_rn(v);
    }
}

// W[m][n] fp32 (4096x4096) -> WT[n][m] split bf16
__global__ void transpose_split2_kernel(const float* __restrict__ w,
                                        __nv_bfloat16* __restrict__ hi,
                                        __nv_bfloat16* __restrict__ lo)
{
    __shared__ float tile[32][33];
    const int m0 = blockIdx.y * 32, n0 = blockIdx.x * 32;
    const int tx = threadIdx.x, ty = threadIdx.y;
#pragma unroll
    for (int i = 0; i < 4; i++)
        tile[ty + i * 8][tx] = w[(long long)(m0 + ty + i * 8) * 4096 + n0 + tx];
    __syncthreads();
#pragma unroll
    for (int i = 0; i < 4; i++) {
        float v = tile[tx][ty + i * 8];
        __nv_bfloat16 h = __float2bfloat16_rn(v);
        __nv_bfloat16 l = __float2bfloat16_rn(v - __bfloat162float(h));
        long long o = (long long)(n0 + ty + i * 8) * 4096 + m0 + tx;
        hi[o] = h; lo[o] = l;
    }
}

// w[n] = sum_m Wk[m][n] * bq[m]
__global__ void wvec_kernel(const float* __restrict__ Wk,
                            const float* __restrict__ bq,
                            float* __restrict__ w)
{
    const int n = blockIdx.x * 256 + threadIdx.x;
    float acc = 0.0f;
    for (int m = 0; m < 4096; m++)
        acc += Wk[(long long)m * 4096 + n] * bq[m];
    w[n] = acc;
}

// beta[z*512+d] = 0.125 * sum_n w[n] * qkv_k[z][d][n]
__global__ void beta_kernel(const __nv_bfloat16* __restrict__ qkv_h,
                            const __nv_bfloat16* __restrict__ qkv_l,
                            const float* __restrict__ w,
                            float* __restrict__ beta)
{
    const int bb = blockIdx.x;
    const int z = bb >> 9, d = bb & 511;
    const int b = z >> 3, h = z & 7;
    const long long row = (long long)(b * 8192 + 4096 + h * 512 + d) * 4096;
    __shared__ float red[256];
    const int t = threadIdx.x;
    float acc = 0.0f;
    for (int n = t; n < 4096; n += 256)
        acc += w[n] * (__bfloat162float(qkv_h[row + n]) + __bfloat162float(qkv_l[row + n]));
    red[t] = acc; __syncthreads();
#pragma unroll
    for (int s = 128; s > 0; s >>= 1) {
        if (t < s) red[t] += red[t + s];
        __syncthreads();
    }
    if (t == 0) beta[bb] = 0.125f * red[0];
}

// softmax over rows of 512 with per-column beta, output fp16
__global__ void softmax_f16_kernel(const float* __restrict__ dot,
                                   const float* __restrict__ beta,
                                   __half* __restrict__ attn)
{
    const long long row = blockIdx.x;
    const float* p = dot + row * 512;
    const float* bb = beta + ((row >> 9) << 9);
    __shared__ float red[256];
    const int t = threadIdx.x;
    float v0 = p[t] + bb[t], v1 = p[t + 256] + bb[t + 256];
    red[t] = fmaxf(v0, v1); __syncthreads();
#pragma unroll
    for (int s = 128; s > 0; s >>= 1) {
        if (t < s) red[t] = fmaxf(red[t], red[t + s]);
        __syncthreads();
    }
    float mx = red[0]; __syncthreads();
    float e0 = expf(v0 - mx), e1 = expf(v1 - mx);
    red[t] = e0 + e1; __syncthreads();
#pragma unroll
    for (int s = 128; s > 0; s >>= 1) {
        if (t < s) red[t] += red[t + s];
        __syncthreads();
    }
    float inv = 1.0f / red[0];
    attn[row * 512 + t]       = __float2half_rn(e0 * inv);
    attn[row * 512 + t + 256] = __float2half_rn(e1 * inv);
}

// ---- host --------------------------------------------------------------------
extern "C" void kernel_launch(void* const* d_in, const int* in_sizes, int n_in,
                              void* d_out, int out_size)
{
    const float* x    = (const float*)d_in[0];
    const float* Wqkv = (const float*)d_in[1];
    const float* bqkv = (const float*)d_in[2];
    const float* Wq   = (const float*)d_in[3];
    const float* bq   = (const float*)d_in[4];
    const float* Wk   = (const float*)d_in[5];
    const float* bk   = (const float*)d_in[6];
    const float* Wv   = (const float*)d_in[7];
    const float* bv   = (const float*)d_in[8];
    const float* Wout = (const float*)d_in[9];
    const float* bout = (const float*)d_in[10];
    float* y = (float*)d_out;
    (void)bk;  // bk-dependent logit terms are row-constant -> cancel in softmax

    __nv_bfloat16 *xT_h, *xT_l, *Wqkv_h, *Wqkv_l, *WqT_h, *WqT_l, *WkT_h, *WkT_l,
        *qkv_h, *qkv_l, *q2_h, *q2_l, *H_h, *H_l;
    __half *xT_f, *Wqkv_vf, *Wv_f, *Wout_f, *v_f, *v2T_f, *attn_f, *outT_f;
    float *dot, *wvec, *beta;
    cudaGetSymbolAddress((void**)&xT_h,   g_xT_hi);   cudaGetSymbolAddress((void**)&xT_l,   g_xT_lo);
    cudaGetSymbolAddress((void**)&xT_f,   g_xT_f);
    cudaGetSymbolAddress((void**)&Wqkv_h, g_Wqkv_hi); cudaGetSymbolAddress((void**)&Wqkv_l, g_Wqkv_lo);
    cudaGetSymbolAddress((void**)&Wqkv_vf,g_Wqkv_vf);
    cudaGetSymbolAddress((void**)&WqT_h,  g_WqT_hi);  cudaGetSymbolAddress((void**)&WqT_l,  g_WqT_lo);
    cudaGetSymbolAddress((void**)&WkT_h,  g_WkT_hi);  cudaGetSymbolAddress((void**)&WkT_l,  g_WkT_lo);
    cudaGetSymbolAddress((void**)&Wv_f,   g_Wv_f);    cudaGetSymbolAddress((void**)&Wout_f, g_Wout_f);
    cudaGetSymbolAddress((void**)&qkv_h,  g_qkv_hi);  cudaGetSymbolAddress((void**)&qkv_l,  g_qkv_lo);
    cudaGetSymbolAddress((void**)&v_f,    g_v_f);
    cudaGetSymbolAddress((void**)&q2_h,   g_q2_hi);   cudaGetSymbolAddress((void**)&q2_l,   g_q2_lo);
    cudaGetSymbolAddress((void**)&H_h,    g_H_hi);    cudaGetSymbolAddress((void**)&H_l,    g_H_lo);
    cudaGetSymbolAddress((void**)&v2T_f,  g_v2T_f);
    cudaGetSymbolAddress((void**)&attn_f, g_attn_f);
    cudaGetSymbolAddress((void**)&outT_f, g_outT_f);
    cudaGetSymbolAddress((void**)&dot,    g_dot);
    cudaGetSymbolAddress((void**)&wvec,   g_wvec);
    cudaGetSymbolAddress((void**)&beta,   g_beta);

    cudaFuncSetAttribute(hmma_gemm, cudaFuncAttributeMaxDynamicSharedMemorySize, SMEM_REQ);
    cudaFuncSetAttribute(hmma_gemm_f16, cudaFuncAttributeMaxDynamicSharedMemorySize, SMEM_REQ_H);

    // conversions
    transpose_split_kernel<<<dim3(128, 128, 2), dim3(32, 8)>>>(x, xT_h, xT_l, xT_f);
    split_kernel<<<32768, 256>>>((const float4*)Wqkv, (uint2*)Wqkv_h, (uint2*)Wqkv_l, 8388608);
    transpose_split2_kernel<<<dim3(128, 128, 1), dim3(32, 8)>>>(Wq, WqT_h, WqT_l);
    transpose_split2_kernel<<<dim3(128, 128, 1), dim3(32, 8)>>>(Wk, WkT_h, WkT_l);
    half_kernel<<<16384, 256>>>((const float4*)(Wqkv + 33554432LL), (uint2*)Wqkv_vf, 4194304);
    wvec_kernel<<<16, 256>>>(Wk, bq, wvec);

    GemmP p;
    // Stage 1qk: qkv_qk[b] = Wqkv[0:8192] @ xT[b]^T + bqkv -> split [2][8192][4096]
    p = {64, 4096, 4096, 0, 0,  0, 0, 0,  4096, 0, 0,  33554432LL, 0,
         4096, 1, 1, bqkv, nullptr, qkv_h, qkv_l, 1.0f};
    hmma_gemm<<<dim3(32, 32, 2), 256, SMEM_REQ>>>(Wqkv_h, Wqkv_l, xT_h, xT_l, p);

    half_kernel<<<16384, 256>>>((const float4*)Wv,   (uint2*)Wv_f,   4194304);
    half_kernel<<<16384, 256>>>((const float4*)Wout, (uint2*)Wout_f, 4194304);

    // H[n'][n] = sum_m Wk[m][n'] Wq[m][n]  (once) -> split [4096][4096]
    p = {64, 4096, 4096, 0, 0,  0, 0, 0,  0, 0, 0,  0LL, 0LL,
         4096, 0, 1, nullptr, nullptr, H_h, H_l, 1.0f};
    hmma_gemm<<<dim3(32, 16, 1), 256, SMEM_REQ>>>(WkT_h, WkT_l, WqT_h, WqT_l, p);

    // Stage 1v (fp16): v[b] = Wqkv_v @ xT[b]^T + bqkv_v -> fp16 [2][4096][4096]
    p = {64, 4096, 4096, 0, 0,  0, 0, 0,  4096, 0, 0,  16777216LL, 0,
         4096, 1, 2, bqkv + 8192, nullptr, (__nv_bfloat16*)v_f, nullptr, 1.0f};
    hmma_gemm_f16<<<dim3(32, 16, 2), 256, SMEM_REQ_H>>>(Wqkv_vf, xT_f, p);

    // qG[z] = qkv_q[z] @ H^T(NT) -> split (replaces q2; no bias)
    p = {64, 4096, 4096, 3, 7,  8192, 512, 0,  0, 0, 0,  16777216LL, 2097152LL,
         4096, 0, 1, nullptr, nullptr, q2_h, q2_l, 1.0f};
    hmma_gemm<<<dim3(32, 2, 16), 256, SMEM_REQ>>>(qkv_h, qkv_l, H_h, H_l, p);

    // beta[z][d] = 0.125 * w . qkv_k[z][d]
    beta_kernel<<<8192, 256>>>(qkv_h, qkv_l, wvec, beta);

    // Stage 2v (fp16, transposed): v2T[b][h][m][d] = Wv[m] . v[z][d] + bv[m]
    p = {64, 4096, 4096, 3, 7,  0, 0, 0,  4096, 512, 0,  16777216LL, 2097152LL,
         512, 1, 2, bv, nullptr, (__nv_bfloat16*)v2T_f, nullptr, 1.0f};
    hmma_gemm_f16<<<dim3(4, 16, 16), 256, SMEM_REQ_H>>>(Wv_f, v_f, p);

    // logits core: dot[z] = 0.125 * qG[z] @ qkv_k[z]^T -> fp32
    p = {64, 4096, 4096, 3, 7,  4096, 512, 0,  8192, 512, 4096,  2097152LL, 262144LL,
         512, 0, 0, nullptr, dot, nullptr, nullptr, 0.125f};
    hmma_gemm<<<dim3(4, 2, 16), 256, SMEM_REQ>>>(q2_h, q2_l, qkv_h, qkv_l, p);

    // softmax(+beta) -> fp16
    softmax_f16_kernel<<<8192, 256>>>(dot, beta, attn_f);

    // Stage 5 (fp16, transposed): outT[b][m][h*512+c] = v2T[z][m] . attn[z][c]
    p = {8, 512, 512, 3, 7,  32768, 4096, 0,  4096, 512, 0,  16777216LL, 512LL,
         4096, 0, 2, nullptr, nullptr, (__nv_bfloat16*)outT_f, nullptr, 1.0f};
    hmma_gemm_f16<<<dim3(4, 16, 16), 256, SMEM_REQ_H>>>(v2T_f, attn_f, p);

    // Stage 6 (fp16): y[b] = Wout @ outT[b]^T + bout -> fp32 d_out
    p = {64, 4096, 4096, 0, 0,  0, 0, 0,  4096, 0, 0,  16777216LL, 0,
         4096, 1, 0, bout, y, nullptr, nullptr, 1.0f};
    hmma_gemm_f16<<<dim3(32, 16, 2), 256, SMEM_REQ_H>>>(Wout_f, outT_f, p);

    (void)in_sizes; (void)n_in; (void)out_size;
}

// round 13
// speedup vs baseline: 1.5109x; 1.0177x over previous
#include <cuda_runtime.h>
#include <cuda_bf16.h>
#include <cuda_fp16.h>
#include <cstdint>

// ============================================================================
// Mixed-precision HMMA pipeline. All GEMMs NT: D[m][n] = sum_k A[m][k]B[n][k].
//  - Pre-softmax path: split-bf16 3-term, fp32 accum. 256x128x64 tile, 1 CTA/SM.
//  - v-chain + post-softmax: fp16 1-term. 128x128x64 tile, 3-stage, 2 CTA/SM.
// Logit path via associativity: logits ~ 0.125*(qkv_q.H.qkv_k^T) + 0.125*beta
//   H = Wk^T Wq (once), beta[d] = (Wk^T bq) . qkv_k[d,:]
// ============================================================================

#define PADK 72
#define A_TILE_ELT (256 * PADK)
#define B_TILE_ELT (128 * PADK)
#define STG_ELT (2 * A_TILE_ELT + 2 * B_TILE_ELT)
#define STG_BYTES (STG_ELT * 2)
#define SMEM_REQ (2 * STG_BYTES)
#define OFF_AL (A_TILE_ELT * 2)
#define OFF_BH (2 * A_TILE_ELT * 2)
#define OFF_BL (2 * A_TILE_ELT * 2 + B_TILE_ELT * 2)

// fp16 kernel: 128x128 tile, 3 stages, 2 CTAs/SM
#define AH_TILE_ELT (128 * PADK)                 // 9216
#define STG_ELT_H (2 * AH_TILE_ELT)              // A + B
#define STG_BYTES_H (STG_ELT_H * 2)              // 36864
#define SMEM_REQ_H (3 * STG_BYTES_H)             // 110592
#define OFF_B_H (AH_TILE_ELT * 2)

// ---- scratch (device globals) ----------------------------------------------
__device__ __align__(256) __nv_bfloat16 g_xT_hi[33554432],  g_xT_lo[33554432];
__device__ __align__(256) __half        g_xT_f[33554432];
__device__ __align__(256) __nv_bfloat16 g_Wqkv_hi[33554432],g_Wqkv_lo[33554432];
__device__ __align__(256) __half        g_Wqkv_vf[16777216];
__device__ __align__(256) __nv_bfloat16 g_WqT_hi[16777216], g_WqT_lo[16777216];
__device__ __align__(256) __nv_bfloat16 g_WkT_hi[16777216], g_WkT_lo[16777216];
__device__ __align__(256) __half        g_Wv_f[16777216],   g_Wout_f[16777216];
__device__ __align__(256) __nv_bfloat16 g_qkv_hi[67108864], g_qkv_lo[67108864];
__device__ __align__(256) __half        g_v_f[33554432];
__device__ __align__(256) __nv_bfloat16 g_q2_hi[33554432],  g_q2_lo[33554432];
__device__ __align__(256) __nv_bfloat16 g_H_hi[16777216],   g_H_lo[16777216];
__device__ __align__(256) __half        g_v2T_f[33554432];
__device__ __align__(256) __half        g_attn_f[4194304];
__device__ __align__(256) __half        g_outT_f[33554432];
__device__ __align__(256) float g_dot[4194304];
__device__ __align__(256) float g_wvec[4096];
__device__ __align__(256) float g_beta[8192];

// ---- helpers ----------------------------------------------------------------
__device__ __forceinline__ uint32_t smem_u32(const void* p) {
    uint32_t r;
    asm("{ .reg .u64 t; cvta.to.shared.u64 t, %1; cvt.u32.u64 %0, t; }" : "=r"(r) : "l"(p));
    return r;
}
__device__ __forceinline__ void cpasync16(uint32_t dst, const void* src) {
    asm volatile("cp.async.cg.shared.global [%0], [%1], 16;" :: "r"(dst), "l"(src));
}
__device__ __forceinline__ void mma16816(float* c, const uint32_t* a, const uint32_t* b) {
    asm volatile(
        "mma.sync.aligned.m16n8k16.row.col.f32.bf16.bf16.f32 "
        "{%0,%1,%2,%3}, {%4,%5,%6,%7}, {%8,%9}, {%0,%1,%2,%3};"
        : "+f"(c[0]), "+f"(c[1]), "+f"(c[2]), "+f"(c[3])
        : "r"(a[0]), "r"(a[1]), "r"(a[2]), "r"(a[3]), "r"(b[0]), "r"(b[1]));
}
__device__ __forceinline__ void mma16816h(float* c, const uint32_t* a, const uint32_t* b) {
    asm volatile(
        "mma.sync.aligned.m16n8k16.row.col.f32.f16.f16.f32 "
        "{%0,%1,%2,%3}, {%4,%5,%6,%7}, {%8,%9}, {%0,%1,%2,%3};"
        : "+f"(c[0]), "+f"(c[1]), "+f"(c[2]), "+f"(c[3])
        : "r"(a[0]), "r"(a[1]), "r"(a[2]), "r"(a[3]), "r"(b[0]), "r"(b[1]));
}
__device__ __forceinline__ void split2(float a, float b, uint32_t& hi, uint32_t& lo) {
    __nv_bfloat16 h0 = __float2bfloat16_rn(a), h1 = __float2bfloat16_rn(b);
    __nv_bfloat16 l0 = __float2bfloat16_rn(a - __bfloat162float(h0));
    __nv_bfloat16 l1 = __float2bfloat16_rn(b - __bfloat162float(h1));
    hi = (uint32_t)__bfloat16_as_ushort(h0) | ((uint32_t)__bfloat16_as_ushort(h1) << 16);
    lo = (uint32_t)__bfloat16_as_ushort(l0) | ((uint32_t)__bfloat16_as_ushort(l1) << 16);
}
__device__ __forceinline__ uint32_t packh2(float a, float b) {
    __half2 h = __floats2half2_rn(a, b);
    return *(uint32_t*)&h;
}

// ---- GEMM params --------------------------------------------------------------
struct GemmP {
    int nk, ldA, ldB, zshift, zmask;
    int aZ1, aZ2, aConst;
    int bZ1, bZ2, bConst;
    long long cZ1, cZ2;
    int ldC, biasMode, outMode;
    const float* bias;
    float* Cf;
    __nv_bfloat16* Chi; __nv_bfloat16* Clo;
    float alpha;
};

// ---- bf16 3-term GEMM (proven best; unchanged) ---------------------------------
__global__ void __launch_bounds__(256, 1)
hmma_gemm(const __nv_bfloat16* __restrict__ Ahg, const __nv_bfloat16* __restrict__ Alg,
          const __nv_bfloat16* __restrict__ Bhg, const __nv_bfloat16* __restrict__ Blg,
          const GemmP p)
{
    extern __shared__ __align__(16) __nv_bfloat16 sm[];
    const int tid = threadIdx.x, lane = tid & 31, wid = tid >> 5;
    const int wm = (wid >> 1) * 64, wn = (wid & 1) * 64;
    const int zh = blockIdx.z >> p.zshift, zl = blockIdx.z & p.zmask;
    const long long arow0 = (long long)p.aZ1 * zh + p.aZ2 * zl + p.aConst
                            + (long long)blockIdx.y * 256;
    const long long brow0 = (long long)p.bZ1 * zh + p.bZ2 * zl + p.bConst
                            + (long long)blockIdx.x * 128;
    const __nv_bfloat16* gAh = Ahg + arow0 * p.ldA;
    const __nv_bfloat16* gAl = Alg + arow0 * p.ldA;
    const __nv_bfloat16* gBh = Bhg + brow0 * p.ldB;
    const __nv_bfloat16* gBl = Blg + brow0 * p.ldB;
    const uint32_t smbase = smem_u32(sm);
    const int ldA = p.ldA, ldB = p.ldB, nk = p.nk;

    auto load_stage = [&](int st, int kb) {
        const uint32_t sb = smbase + (uint32_t)st * STG_BYTES;
        const long long koff = (long long)kb * 64;
#pragma unroll
        for (int i = 0; i < 8; i++) {
            const int c = tid + i * 256;
            const int row = c >> 3, ch = c & 7;
            const uint32_t doff = (uint32_t)(row * PADK + ch * 8) * 2;
            const long long ga = (long long)row * ldA + koff + ch * 8;
            cpasync16(sb + doff, gAh + ga);
            cpasync16(sb + OFF_AL + doff, gAl + ga);
        }
#pragma unroll
        for (int i = 0; i < 4; i++) {
            const int c = tid + i * 256;
            const int row = c >> 3, ch = c & 7;
            const uint32_t doff = (uint32_t)(row * PADK + ch * 8) * 2;
            const long long gb = (long long)row * ldB + koff + ch * 8;
            cpasync16(sb + OFF_BH + doff, gBh + gb);
            cpasync16(sb + OFF_BL + doff, gBl + gb);
        }
        asm volatile("cp.async.commit_group;" ::: "memory");
    };

    load_stage(0, 0);
    load_stage(1, 1);

    float acc[4][8][4];
#pragma unroll
    for (int a = 0; a < 4; a++)
#pragma unroll
        for (int b = 0; b < 8; b++)
#pragma unroll
            for (int c = 0; c < 4; c++) acc[a][b][c] = 0.0f;

    const int krow = (lane & 3) * 2;
    const int grow = lane >> 2;

    for (int kb = 0; kb < nk; kb++) {
        asm volatile("cp.async.wait_group 1;" ::: "memory");
        __syncthreads();
        const int st = kb & 1;
        const __nv_bfloat16* sAh = sm + (size_t)st * STG_ELT;
        const __nv_bfloat16* sAl = sAh + A_TILE_ELT;
        const __nv_bfloat16* sBh = sAl + A_TILE_ELT;
        const __nv_bfloat16* sBl = sBh + B_TILE_ELT;

#pragma unroll
        for (int k16 = 0; k16 < 4; k16++) {
            const int kk = k16 * 16 + krow;
            uint32_t ah[4][4], al[4][4];
#pragma unroll
            for (int mt = 0; mt < 4; mt++) {
                const int r0 = (wm + mt * 16 + grow) * PADK;
                const int r1 = r0 + 8 * PADK;
                ah[mt][0] = *(const uint32_t*)(sAh + r0 + kk);
                ah[mt][1] = *(const uint32_t*)(sAh + r1 + kk);
                ah[mt][2] = *(const uint32_t*)(sAh + r0 + kk + 8);
                ah[mt][3] = *(const uint32_t*)(sAh + r1 + kk + 8);
                al[mt][0] = *(const uint32_t*)(sAl + r0 + kk);
                al[mt][1] = *(const uint32_t*)(sAl + r1 + kk);
                al[mt][2] = *(const uint32_t*)(sAl + r0 + kk + 8);
                al[mt][3] = *(const uint32_t*)(sAl + r1 + kk + 8);
            }
#pragma unroll
            for (int nt = 0; nt < 8; nt++) {
                const int r = (wn + nt * 8 + grow) * PADK;
                uint32_t bh[2], bl[2];
                bh[0] = *(const uint32_t*)(sBh + r + kk);
                bh[1] = *(const uint32_t*)(sBh + r + kk + 8);
                bl[0] = *(const uint32_t*)(sBl + r + kk);
                bl[1] = *(const uint32_t*)(sBl + r + kk + 8);
#pragma unroll
                for (int mt = 0; mt < 4; mt++)
                    mma16816(acc[mt][nt], ah[mt], bh);
#pragma unroll
                for (int mt = 0; mt < 4; mt++)
                    mma16816(acc[mt][nt], ah[mt], bl);
#pragma unroll
                for (int mt = 0; mt < 4; mt++)
                    mma16816(acc[mt][nt], al[mt], bh);
            }
        }
        __syncthreads();
        if (kb + 2 < nk) load_stage(st, kb + 2);
    }

    const long long cbase = p.cZ1 * zh + p.cZ2 * zl;
    const int n0 = blockIdx.x * 128 + wn + (lane & 3) * 2;
    const int m0 = blockIdx.y * 256 + wm + (lane >> 2);
#pragma unroll
    for (int mt = 0; mt < 4; mt++) {
#pragma unroll
        for (int half = 0; half < 2; half++) {
            const int m = m0 + mt * 16 + half * 8;
            const float bm = (p.biasMode == 1) ? p.bias[m] : 0.0f;
            const long long rowoff = cbase + (long long)m * p.ldC;
#pragma unroll
            for (int nt = 0; nt < 8; nt++) {
                const int n = n0 + nt * 8;
                float v0 = acc[mt][nt][half * 2 + 0] * p.alpha + bm;
                float v1 = acc[mt][nt][half * 2 + 1] * p.alpha + bm;
                if (p.biasMode == 2) { v0 += p.bias[n]; v1 += p.bias[n + 1]; }
                if (p.outMode == 0) {
                    *(float2*)(p.Cf + rowoff + n) = make_float2(v0, v1);
                } else {
                    uint32_t h, l;
                    split2(v0, v1, h, l);
                    *(uint32_t*)(p.Chi + rowoff + n) = h;
                    *(uint32_t*)(p.Clo + rowoff + n) = l;
                }
            }
        }
    }
}

// ---- fp16 1-term GEMM: 128x128x64 tile, 4 warps, 3 stages, 2 CTAs/SM -----------
__global__ void __launch_bounds__(128, 2)
hmma_gemm_f16(const __half* __restrict__ Ag, const __half* __restrict__ Bg,
              const GemmP p)
{
    extern __shared__ __align__(16) __half smh[];
    const int tid = threadIdx.x, lane = tid & 31, wid = tid >> 5;
    const int wm = (wid >> 1) * 64, wn = (wid & 1) * 64;
    const int zh = blockIdx.z >> p.zshift, zl = blockIdx.z & p.zmask;
    const long long arow0 = (long long)p.aZ1 * zh + p.aZ2 * zl + p.aConst
                            + (long long)blockIdx.y * 128;
    const long long brow0 = (long long)p.bZ1 * zh + p.bZ2 * zl + p.bConst
                            + (long long)blockIdx.x * 128;
    const __half* gA = Ag + arow0 * p.ldA;
    const __half* gB = Bg + brow0 * p.ldB;
    const uint32_t smbase = smem_u32(smh);
    const int ldA = p.ldA, ldB = p.ldB, nk = p.nk;

    auto load_stage = [&](int st, int kb) {
        const uint32_t sb = smbase + (uint32_t)st * STG_BYTES_H;
        const long long koff = (long long)kb * 64;
#pragma unroll
        for (int i = 0; i < 8; i++) {
            const int c = tid + i * 128;       // 0..1023 (128 rows x 8 chunks)
            const int row = c >> 3, ch = c & 7;
            const uint32_t doff = (uint32_t)(row * PADK + ch * 8) * 2;
            cpasync16(sb + doff, gA + (long long)row * ldA + koff + ch * 8);
            cpasync16(sb + OFF_B_H + doff, gB + (long long)row * ldB + koff + ch * 8);
        }
        asm volatile("cp.async.commit_group;" ::: "memory");
    };

    // prologue: 3 stages in flight (all fp16 stages have nk >= 3)
    load_stage(0, 0);
    load_stage(1, 1);
    load_stage(2, 2);

    float acc[4][8][4];
#pragma unroll
    for (int a = 0; a < 4; a++)
#pragma unroll
        for (int b = 0; b < 8; b++)
#pragma unroll
            for (int c = 0; c < 4; c++) acc[a][b][c] = 0.0f;

    const int krow = (lane & 3) * 2;
    const int grow = lane >> 2;

    for (int kb = 0; kb < nk; kb++) {
        asm volatile("cp.async.wait_group 2;" ::: "memory");
        __syncthreads();
        const int st = kb % 3;
        const __half* sA = smh + (size_t)st * STG_ELT_H;
        const __half* sB = sA + AH_TILE_ELT;

#pragma unroll
        for (int k16 = 0; k16 < 4; k16++) {
            const int kk = k16 * 16 + krow;
            uint32_t ah[4][4];
#pragma unroll
            for (int mt = 0; mt < 4; mt++) {
                const int r0 = (wm + mt * 16 + grow) * PADK;
                const int r1 = r0 + 8 * PADK;
                ah[mt][0] = *(const uint32_t*)(sA + r0 + kk);
                ah[mt][1] = *(const uint32_t*)(sA + r1 + kk);
                ah[mt][2] = *(const uint32_t*)(sA + r0 + kk + 8);
                ah[mt][3] = *(const uint32_t*)(sA + r1 + kk + 8);
            }
#pragma unroll
            for (int nt = 0; nt < 8; nt++) {
                const int r = (wn + nt * 8 + grow) * PADK;
                uint32_t bh[2];
                bh[0] = *(const uint32_t*)(sB + r + kk);
                bh[1] = *(const uint32_t*)(sB + r + kk + 8);
#pragma unroll
                for (int mt = 0; mt < 4; mt++)
                    mma16816h(acc[mt][nt], ah[mt], bh);
            }
        }
        __syncthreads();
        if (kb + 3 < nk) load_stage(st, kb + 3);
    }

    const long long cbase = p.cZ1 * zh + p.cZ2 * zl;
    const int n0 = blockIdx.x * 128 + wn + (lane & 3) * 2;
    const int m0 = blockIdx.y * 128 + wm + (lane >> 2);
    __half* Ch = (__half*)p.Chi;
#pragma unroll
    for (int mt = 0; mt < 4; mt++) {
#pragma unroll
        for (int half = 0; half < 2; half++) {
            const int m = m0 + mt * 16 + half * 8;
            const float bm = (p.biasMode == 1) ? p.bias[m] : 0.0f;
            const long long rowoff = cbase + (long long)m * p.ldC;
#pragma unroll
            for (int nt = 0; nt < 8; nt++) {
                const int n = n0 + nt * 8;
                float v0 = acc[mt][nt][half * 2 + 0] * p.alpha + bm;
                float v1 = acc[mt][nt][half * 2 + 1] * p.alpha + bm;
                if (p.biasMode == 2) { v0 += p.bias[n]; v1 += p.bias[n + 1]; }
                if (p.outMode == 0) {
                    *(float2*)(p.Cf + rowoff + n) = make_float2(v0, v1);
                } else {
                    *(uint32_t*)(Ch + rowoff + n) = packh2(v0, v1);
                }
            }
        }
    }
}

// ---- conversions -------------------------------------------------------------
__global__ void split_kernel(const float4* __restrict__ in, uint2* __restrict__ hi,
                             uint2* __restrict__ lo, int n4)
{
    int i = blockIdx.x * 256 + threadIdx.x;
    if (i >= n4) return;
    float4 v = in[i];
    uint32_t h0, l0, h1, l1;
    split2(v.x, v.y, h0, l0);
    split2(v.z, v.w, h1, l1);
    hi[i] = make_uint2(h0, h1);
    lo[i] = make_uint2(l0, l1);
}

__global__ void half_kernel(const float4* __restrict__ in, uint2* __restrict__ out,
                            int n4)
{
    int i = blockIdx.x * 256 + threadIdx.x;
    if (i >= n4) return;
    float4 v = in[i];
    out[i] = make_uint2(packh2(v.x, v.y), packh2(v.z, v.w));
}

// x[b][c][n] fp32 -> xT[b][n][c] split bf16 + fp16 (4096x4096 per batch)
__global__ void transpose_split_kernel(const float* __restrict__ x,
                                       __nv_bfloat16* __restrict__ hi,
                                       __nv_bfloat16* __restrict__ lo,
                                       __half* __restrict__ hf)
{
    __shared__ float tile[32][33];
    const int b = blockIdx.z;
    const int c0 = blockIdx.y * 32, n0 = blockIdx.x * 32;
    const int tx = threadIdx.x, ty = threadIdx.y;
    const float* xb = x + (long long)b * 16777216;
#pragma unroll
    for (int i = 0; i < 4; i++)
        tile[ty + i * 8][tx] = xb[(long long)(c0 + ty + i * 8) * 4096 + n0 + tx];
    __syncthreads();
#pragma unroll
    for (int i = 0; i < 4; i++) {
        float v = tile[tx][ty + i * 8];
        __nv_bfloat16 h = __float2bfloat16_rn(v);
        __nv_bfloat16 l = __float2bfloat16_rn(v - __bfloat162float(h));
        long long o = (long long)b * 16777216 + (long long)(n0 + ty + i * 8) * 4096 + c0 + tx;
        hi[o] = h; lo[o] = l; hf[o] = __float2half_rn(v);
    }
}

// W[m][n] fp32 (4096x4096) -> WT[n][m] split bf16
__global__ void transpose_split2_kernel(const float* __restrict__ w,
                                        __nv_bfloat16* __restrict__ hi,
                                        __nv_bfloat16* __restrict__ lo)
{
    __shared__ float tile[32][33];
    const int m0 = blockIdx.y * 32, n0 = blockIdx.x * 32;
    const int tx = threadIdx.x, ty = threadIdx.y;
#pragma unroll
    for (int i = 0; i < 4; i++)
        tile[ty + i * 8][tx] = w[(long long)(m0 + ty + i * 8) * 4096 + n0 + tx];
    __syncthreads();
#pragma unroll
    for (int i = 0; i < 4; i++) {
        float v = tile[tx][ty + i * 8];
        __nv_bfloat16 h = __float2bfloat16_rn(v);
        __nv_bfloat16 l = __float2bfloat16_rn(v - __bfloat162float(h));
        long long o = (long long)(n0 + ty + i * 8) * 4096 + m0 + tx;
        hi[o] = h; lo[o] = l;
    }
}

// w[n] = sum_m Wk[m][n] * bq[m]
__global__ void wvec_kernel(const float* __restrict__ Wk,
                            const float* __restrict__ bq,
                            float* __restrict__ w)
{
    const int n = blockIdx.x * 256 + threadIdx.x;
    float acc = 0.0f;
    for (int m = 0; m < 4096; m++)
        acc += Wk[(long long)m * 4096 + n] * bq[m];
    w[n] = acc;
}

// beta[z*512+d] = 0.125 * sum_n w[n] * qkv_k[z][d][n]
__global__ void beta_kernel(const __nv_bfloat16* __restrict__ qkv_h,
                            const __nv_bfloat16* __restrict__ qkv_l,
                            const float* __restrict__ w,
                            float* __restrict__ beta)
{
    const int bb = blockIdx.x;
    const int z = bb >> 9, d = bb & 511;
    const int b = z >> 3, h = z & 7;
    const long long row = (long long)(b * 8192 + 4096 + h * 512 + d) * 4096;
    __shared__ float red[256];
    const int t = threadIdx.x;
    float acc = 0.0f;
    for (int n = t; n < 4096; n += 256)
        acc += w[n] * (__bfloat162float(qkv_h[row + n]) + __bfloat162float(qkv_l[row + n]));
    red[t] = acc; __syncthreads();
#pragma unroll
    for (int s = 128; s > 0; s >>= 1) {
        if (t < s) red[t] += red[t + s];
        __syncthreads();
    }
    if (t == 0) beta[bb] = 0.125f * red[0];
}

// softmax over rows of 512 with per-column beta, output fp16
__global__ void softmax_f16_kernel(const float* __restrict__ dot,
                                   const float* __restrict__ beta,
                                   __half* __restrict__ attn)
{
    const long long row = blockIdx.x;
    const float* p = dot + row * 512;
    const float* bb = beta + ((row >> 9) << 9);
    __shared__ float red[256];
    const int t = threadIdx.x;
    float v0 = p[t] + bb[t], v1 = p[t + 256] + bb[t + 256];
    red[t] = fmaxf(v0, v1); __syncthreads();
#pragma unroll
    for (int s = 128; s > 0; s >>= 1) {
        if (t < s) red[t] = fmaxf(red[t], red[t + s]);
        __syncthreads();
    }
    float mx = red[0]; __syncthreads();
    float e0 = expf(v0 - mx), e1 = expf(v1 - mx);
    red[t] = e0 + e1; __syncthreads();
#pragma unroll
    for (int s = 128; s > 0; s >>= 1) {
        if (t < s) red[t] += red[t + s];
        __syncthreads();
    }
    float inv = 1.0f / red[0];
    attn[row * 512 + t]       = __float2half_rn(e0 * inv);
    attn[row * 512 + t + 256] = __float2half_rn(e1 * inv);
}

// ---- host --------------------------------------------------------------------
extern "C" void kernel_launch(void* const* d_in, const int* in_sizes, int n_in,
                              void* d_out, int out_size)
{
    const float* x    = (const float*)d_in[0];
    const float* Wqkv = (const float*)d_in[1];
    const float* bqkv = (const float*)d_in[2];
    const float* Wq   = (const float*)d_in[3];
    const float* bq   = (const float*)d_in[4];
    const float* Wk   = (const float*)d_in[5];
    const float* bk   = (const float*)d_in[6];
    const float* Wv   = (const float*)d_in[7];
    const float* bv   = (const float*)d_in[8];
    const float* Wout = (const float*)d_in[9];
    const float* bout = (const float*)d_in[10];
    float* y = (float*)d_out;
    (void)bk;  // bk logit terms are row-constant -> cancel in softmax

    __nv_bfloat16 *xT_h, *xT_l, *Wqkv_h, *Wqkv_l, *WqT_h, *WqT_l, *WkT_h, *WkT_l,
        *qkv_h, *qkv_l, *q2_h, *q2_l, *H_h, *H_l;
    __half *xT_f, *Wqkv_vf, *Wv_f, *Wout_f, *v_f, *v2T_f, *attn_f, *outT_f;
    float *dot, *wvec, *beta;
    cudaGetSymbolAddress((void**)&xT_h,   g_xT_hi);   cudaGetSymbolAddress((void**)&xT_l,   g_xT_lo);
    cudaGetSymbolAddress((void**)&xT_f,   g_xT_f);
    cudaGetSymbolAddress((void**)&Wqkv_h, g_Wqkv_hi); cudaGetSymbolAddress((void**)&Wqkv_l, g_Wqkv_lo);
    cudaGetSymbolAddress((void**)&Wqkv_vf,g_Wqkv_vf);
    cudaGetSymbolAddress((void**)&WqT_h,  g_WqT_hi);  cudaGetSymbolAddress((void**)&WqT_l,  g_WqT_lo);
    cudaGetSymbolAddress((void**)&WkT_h,  g_WkT_hi);  cudaGetSymbolAddress((void**)&WkT_l,  g_WkT_lo);
    cudaGetSymbolAddress((void**)&Wv_f,   g_Wv_f);    cudaGetSymbolAddress((void**)&Wout_f, g_Wout_f);
    cudaGetSymbolAddress((void**)&qkv_h,  g_qkv_hi);  cudaGetSymbolAddress((void**)&qkv_l,  g_qkv_lo);
    cudaGetSymbolAddress((void**)&v_f,    g_v_f);
    cudaGetSymbolAddress((void**)&q2_h,   g_q2_hi);   cudaGetSymbolAddress((void**)&q2_l,   g_q2_lo);
    cudaGetSymbolAddress((void**)&H_h,    g_H_hi);    cudaGetSymbolAddress((void**)&H_l,    g_H_lo);
    cudaGetSymbolAddress((void**)&v2T_f,  g_v2T_f);
    cudaGetSymbolAddress((void**)&attn_f, g_attn_f);
    cudaGetSymbolAddress((void**)&outT_f, g_outT_f);
    cudaGetSymbolAddress((void**)&dot,    g_dot);
    cudaGetSymbolAddress((void**)&wvec,   g_wvec);
    cudaGetSymbolAddress((void**)&beta,   g_beta);

    cudaFuncSetAttribute(hmma_gemm, cudaFuncAttributeMaxDynamicSharedMemorySize, SMEM_REQ);
    cudaFuncSetAttribute(hmma_gemm_f16, cudaFuncAttributeMaxDynamicSharedMemorySize, SMEM_REQ_H);

    // conversions
    transpose_split_kernel<<<dim3(128, 128, 2), dim3(32, 8)>>>(x, xT_h, xT_l, xT_f);
    split_kernel<<<32768, 256>>>((const float4*)Wqkv, (uint2*)Wqkv_h, (uint2*)Wqkv_l, 8388608);
    transpose_split2_kernel<<<dim3(128, 128, 1), dim3(32, 8)>>>(Wq, WqT_h, WqT_l);
    transpose_split2_kernel<<<dim3(128, 128, 1), dim3(32, 8)>>>(Wk, WkT_h, WkT_l);
    half_kernel<<<16384, 256>>>((const float4*)(Wqkv + 33554432LL), (uint2*)Wqkv_vf, 4194304);
    wvec_kernel<<<16, 256>>>(Wk, bq, wvec);

    GemmP p;
    // Stage 1qk: qkv_qk[b] = Wqkv[0:8192] @ xT[b]^T + bqkv -> split [2][8192][4096]
    p = {64, 4096, 4096, 0, 0,  0, 0, 0,  4096, 0, 0,  33554432LL, 0,
         4096, 1, 1, bqkv, nullptr, qkv_h, qkv_l, 1.0f};
    hmma_gemm<<<dim3(32, 32, 2), 256, SMEM_REQ>>>(Wqkv_h, Wqkv_l, xT_h, xT_l, p);

    half_kernel<<<16384, 256>>>((const float4*)Wv,   (uint2*)Wv_f,   4194304);
    half_kernel<<<16384, 256>>>((const float4*)Wout, (uint2*)Wout_f, 4194304);

    // H[n'][n] = sum_m Wk[m][n'] Wq[m][n]  (once) -> split [4096][4096]
    p = {64, 4096, 4096, 0, 0,  0, 0, 0,  0, 0, 0,  0LL, 0LL,
         4096, 0, 1, nullptr, nullptr, H_h, H_l, 1.0f};
    hmma_gemm<<<dim3(32, 16, 1), 256, SMEM_REQ>>>(WkT_h, WkT_l, WqT_h, WqT_l, p);

    // Stage 1v (fp16): v[b] = Wqkv_v @ xT[b]^T + bqkv_v -> fp16 [2][4096][4096]
    p = {64, 4096, 4096, 0, 0,  0, 0, 0,  4096, 0, 0,  16777216LL, 0,
         4096, 1, 2, bqkv + 8192, nullptr, (__nv_bfloat16*)v_f, nullptr, 1.0f};
    hmma_gemm_f16<<<dim3(32, 32, 2), 128, SMEM_REQ_H>>>(Wqkv_vf, xT_f, p);

    // qG[z] = qkv_q[z] @ H^T(NT) -> split (replaces q2; no bias)
    p = {64, 4096, 4096, 3, 7,  8192, 512, 0,  0, 0, 0,  16777216LL, 2097152LL,
         4096, 0, 1, nullptr, nullptr, q2_h, q2_l, 1.0f};
    hmma_gemm<<<dim3(32, 2, 16), 256, SMEM_REQ>>>(qkv_h, qkv_l, H_h, H_l, p);

    // beta[z][d] = 0.125 * w . qkv_k[z][d]
    beta_kernel<<<8192, 256>>>(qkv_h, qkv_l, wvec, beta);

    // Stage 2v (fp16, transposed): v2T[b][h][m][d] = Wv[m] . v[z][d] + bv[m]
    p = {64, 4096, 4096, 3, 7,  0, 0, 0,  4096, 512, 0,  16777216LL, 2097152LL,
         512, 1, 2, bv, nullptr, (__nv_bfloat16*)v2T_f, nullptr, 1.0f};
    hmma_gemm_f16<<<dim3(4, 32, 16), 128, SMEM_REQ_H>>>(Wv_f, v_f, p);

    // logits core: dot[z] = 0.125 * qG[z] @ qkv_k[z]^T -> fp32
    p = {64, 4096, 4096, 3, 7,  4096, 512, 0,  8192, 512, 4096,  2097152LL, 262144LL,
         512, 0, 0, nullptr, dot, nullptr, nullptr, 0.125f};
    hmma_gemm<<<dim3(4, 2, 16), 256, SMEM_REQ>>>(q2_h, q2_l, qkv_h, qkv_l, p);

    // softmax(+beta) -> fp16
    softmax_f16_kernel<<<8192, 256>>>(dot, beta, attn_f);

    // Stage 5 (fp16, transposed): outT[b][m][h*512+c] = v2T[z][m] . attn[z][c]
    p = {8, 512, 512, 3, 7,  32768, 4096, 0,  4096, 512, 0,  16777216LL, 512LL,
         4096, 0, 2, nullptr, nullptr, (__nv_bfloat16*)outT_f, nullptr, 1.0f};
    hmma_gemm_f16<<<dim3(4, 32, 16), 128, SMEM_REQ_H>>>(v2T_f, attn_f, p);

    // Stage 6 (fp16): y[b] = Wout @ outT[b]^T + bout -> fp32 d_out
    p = {64, 4096, 4096, 0, 0,  0, 0, 0,  4096, 0, 0,  16777216LL, 0,
         4096, 1, 0, bout, y, nullptr, nullptr, 1.0f};
    hmma_gemm_f16<<<dim3(32, 32, 2), 128, SMEM_REQ_H>>>(Wout_f, outT_f, p);

    (void)in_sizes; (void)n_in; (void)out_size;
}

// round 14
// speedup vs baseline: 1.8047x; 1.1944x over previous
#include <cuda_runtime.h>
#include <cuda_bf16.h>
#include <cuda_fp16.h>
#include <cstdint>

// ============================================================================
// Mixed-precision HMMA pipeline. All GEMMs NT: D[m][n] = sum_k A[m][k]B[n][k].
//  - Pre-softmax path: split-bf16 3-term, fp32 accum. 256x128x64 tile, 1 CTA/SM.
//  - v-chain + post-softmax: fp16 1-term. 128x128x64 tile, 3-stage, 2 CTA/SM.
// Logit path via associativity: logits ~ 0.125*(qkv_q.H.qkv_k^T) + 0.125*beta
// NEW: dual-stream fork-join schedule (conversions/H/fp16-chain/beta/logits-half2
// overlap the bf16 main chain) + split-K x2 logits.
// ============================================================================

#define PADK 72
#define A_TILE_ELT (256 * PADK)
#define B_TILE_ELT (128 * PADK)
#define STG_ELT (2 * A_TILE_ELT + 2 * B_TILE_ELT)
#define STG_BYTES (STG_ELT * 2)
#define SMEM_REQ (2 * STG_BYTES)
#define OFF_AL (A_TILE_ELT * 2)
#define OFF_BH (2 * A_TILE_ELT * 2)
#define OFF_BL (2 * A_TILE_ELT * 2 + B_TILE_ELT * 2)

#define AH_TILE_ELT (128 * PADK)
#define STG_ELT_H (2 * AH_TILE_ELT)
#define STG_BYTES_H (STG_ELT_H * 2)
#define SMEM_REQ_H (3 * STG_BYTES_H)
#define OFF_B_H (AH_TILE_ELT * 2)

// ---- scratch (device globals) ----------------------------------------------
__device__ __align__(256) __nv_bfloat16 g_xT_hi[33554432],  g_xT_lo[33554432];
__device__ __align__(256) __half        g_xT_f[33554432];
__device__ __align__(256) __nv_bfloat16 g_Wqkv_hi[33554432],g_Wqkv_lo[33554432];
__device__ __align__(256) __half        g_Wqkv_vf[16777216];
__device__ __align__(256) __nv_bfloat16 g_WqT_hi[16777216], g_WqT_lo[16777216];
__device__ __align__(256) __nv_bfloat16 g_WkT_hi[16777216], g_WkT_lo[16777216];
__device__ __align__(256) __half        g_Wv_f[16777216],   g_Wout_f[16777216];
__device__ __align__(256) __nv_bfloat16 g_qkv_hi[67108864], g_qkv_lo[67108864];
__device__ __align__(256) __half        g_v_f[33554432];
__device__ __align__(256) __nv_bfloat16 g_q2_hi[33554432],  g_q2_lo[33554432];
__device__ __align__(256) __nv_bfloat16 g_H_hi[16777216],   g_H_lo[16777216];
__device__ __align__(256) __half        g_v2T_f[33554432];
__device__ __align__(256) __half        g_attn_f[4194304];
__device__ __align__(256) __half        g_outT_f[33554432];
__device__ __align__(256) float g_dot[4194304];
__device__ __align__(256) float g_dot2[4194304];
__device__ __align__(256) float g_wvec[4096];
__device__ __align__(256) float g_beta[8192];

// ---- helpers ----------------------------------------------------------------
__device__ __forceinline__ uint32_t smem_u32(const void* p) {
    uint32_t r;
    asm("{ .reg .u64 t; cvta.to.shared.u64 t, %1; cvt.u32.u64 %0, t; }" : "=r"(r) : "l"(p));
    return r;
}
__device__ __forceinline__ void cpasync16(uint32_t dst, const void* src) {
    asm volatile("cp.async.cg.shared.global [%0], [%1], 16;" :: "r"(dst), "l"(src));
}
__device__ __forceinline__ void mma16816(float* c, const uint32_t* a, const uint32_t* b) {
    asm volatile(
        "mma.sync.aligned.m16n8k16.row.col.f32.bf16.bf16.f32 "
        "{%0,%1,%2,%3}, {%4,%5,%6,%7}, {%8,%9}, {%0,%1,%2,%3};"
        : "+f"(c[0]), "+f"(c[1]), "+f"(c[2]), "+f"(c[3])
        : "r"(a[0]), "r"(a[1]), "r"(a[2]), "r"(a[3]), "r"(b[0]), "r"(b[1]));
}
__device__ __forceinline__ void mma16816h(float* c, const uint32_t* a, const uint32_t* b) {
    asm volatile(
        "mma.sync.aligned.m16n8k16.row.col.f32.f16.f16.f32 "
        "{%0,%1,%2,%3}, {%4,%5,%6,%7}, {%8,%9}, {%0,%1,%2,%3};"
        : "+f"(c[0]), "+f"(c[1]), "+f"(c[2]), "+f"(c[3])
        : "r"(a[0]), "r"(a[1]), "r"(a[2]), "r"(a[3]), "r"(b[0]), "r"(b[1]));
}
__device__ __forceinline__ void split2(float a, float b, uint32_t& hi, uint32_t& lo) {
    __nv_bfloat16 h0 = __float2bfloat16_rn(a), h1 = __float2bfloat16_rn(b);
    __nv_bfloat16 l0 = __float2bfloat16_rn(a - __bfloat162float(h0));
    __nv_bfloat16 l1 = __float2bfloat16_rn(b - __bfloat162float(h1));
    hi = (uint32_t)__bfloat16_as_ushort(h0) | ((uint32_t)__bfloat16_as_ushort(h1) << 16);
    lo = (uint32_t)__bfloat16_as_ushort(l0) | ((uint32_t)__bfloat16_as_ushort(l1) << 16);
}
__device__ __forceinline__ uint32_t packh2(float a, float b) {
    __half2 h = __floats2half2_rn(a, b);
    return *(uint32_t*)&h;
}

// ---- GEMM params --------------------------------------------------------------
struct GemmP {
    int nk, ldA, ldB, zshift, zmask;
    int aZ1, aZ2, aConst;
    int bZ1, bZ2, bConst;
    long long cZ1, cZ2;
    int ldC, biasMode, outMode;
    const float* bias;
    float* Cf;
    __nv_bfloat16* Chi; __nv_bfloat16* Clo;
    float alpha;
    int k0 = 0;      // K element offset (split-K)
};

// ---- bf16 3-term GEMM ----------------------------------------------------------
__global__ void __launch_bounds__(256, 1)
hmma_gemm(const __nv_bfloat16* __restrict__ Ahg, const __nv_bfloat16* __restrict__ Alg,
          const __nv_bfloat16* __restrict__ Bhg, const __nv_bfloat16* __restrict__ Blg,
          const GemmP p)
{
    extern __shared__ __align__(16) __nv_bfloat16 sm[];
    const int tid = threadIdx.x, lane = tid & 31, wid = tid >> 5;
    const int wm = (wid >> 1) * 64, wn = (wid & 1) * 64;
    const int zh = blockIdx.z >> p.zshift, zl = blockIdx.z & p.zmask;
    const long long arow0 = (long long)p.aZ1 * zh + p.aZ2 * zl + p.aConst
                            + (long long)blockIdx.y * 256;
    const long long brow0 = (long long)p.bZ1 * zh + p.bZ2 * zl + p.bConst
                            + (long long)blockIdx.x * 128;
    const __nv_bfloat16* gAh = Ahg + arow0 * p.ldA;
    const __nv_bfloat16* gAl = Alg + arow0 * p.ldA;
    const __nv_bfloat16* gBh = Bhg + brow0 * p.ldB;
    const __nv_bfloat16* gBl = Blg + brow0 * p.ldB;
    const uint32_t smbase = smem_u32(sm);
    const int ldA = p.ldA, ldB = p.ldB, nk = p.nk, k0 = p.k0;

    auto load_stage = [&](int st, int kb) {
        const uint32_t sb = smbase + (uint32_t)st * STG_BYTES;
        const long long koff = (long long)kb * 64 + k0;
#pragma unroll
        for (int i = 0; i < 8; i++) {
            const int c = tid + i * 256;
            const int row = c >> 3, ch = c & 7;
            const uint32_t doff = (uint32_t)(row * PADK + ch * 8) * 2;
            const long long ga = (long long)row * ldA + koff + ch * 8;
            cpasync16(sb + doff, gAh + ga);
            cpasync16(sb + OFF_AL + doff, gAl + ga);
        }
#pragma unroll
        for (int i = 0; i < 4; i++) {
            const int c = tid + i * 256;
            const int row = c >> 3, ch = c & 7;
            const uint32_t doff = (uint32_t)(row * PADK + ch * 8) * 2;
            const long long gb = (long long)row * ldB + koff + ch * 8;
            cpasync16(sb + OFF_BH + doff, gBh + gb);
            cpasync16(sb + OFF_BL + doff, gBl + gb);
        }
        asm volatile("cp.async.commit_group;" ::: "memory");
    };

    load_stage(0, 0);
    load_stage(1, 1);

    float acc[4][8][4];
#pragma unroll
    for (int a = 0; a < 4; a++)
#pragma unroll
        for (int b = 0; b < 8; b++)
#pragma unroll
            for (int c = 0; c < 4; c++) acc[a][b][c] = 0.0f;

    const int krow = (lane & 3) * 2;
    const int grow = lane >> 2;

    for (int kb = 0; kb < nk; kb++) {
        asm volatile("cp.async.wait_group 1;" ::: "memory");
        __syncthreads();
        const int st = kb & 1;
        const __nv_bfloat16* sAh = sm + (size_t)st * STG_ELT;
        const __nv_bfloat16* sAl = sAh + A_TILE_ELT;
        const __nv_bfloat16* sBh = sAl + A_TILE_ELT;
        const __nv_bfloat16* sBl = sBh + B_TILE_ELT;

#pragma unroll
        for (int k16 = 0; k16 < 4; k16++) {
            const int kk = k16 * 16 + krow;
            uint32_t ah[4][4], al[4][4];
#pragma unroll
            for (int mt = 0; mt < 4; mt++) {
                const int r0 = (wm + mt * 16 + grow) * PADK;
                const int r1 = r0 + 8 * PADK;
                ah[mt][0] = *(const uint32_t*)(sAh + r0 + kk);
                ah[mt][1] = *(const uint32_t*)(sAh + r1 + kk);
                ah[mt][2] = *(const uint32_t*)(sAh + r0 + kk + 8);
                ah[mt][3] = *(const uint32_t*)(sAh + r1 + kk + 8);
                al[mt][0] = *(const uint32_t*)(sAl + r0 + kk);
                al[mt][1] = *(const uint32_t*)(sAl + r1 + kk);
                al[mt][2] = *(const uint32_t*)(sAl + r0 + kk + 8);
                al[mt][3] = *(const uint32_t*)(sAl + r1 + kk + 8);
            }
#pragma unroll
            for (int nt = 0; nt < 8; nt++) {
                const int r = (wn + nt * 8 + grow) * PADK;
                uint32_t bh[2], bl[2];
                bh[0] = *(const uint32_t*)(sBh + r + kk);
                bh[1] = *(const uint32_t*)(sBh + r + kk + 8);
                bl[0] = *(const uint32_t*)(sBl + r + kk);
                bl[1] = *(const uint32_t*)(sBl + r + kk + 8);
#pragma unroll
                for (int mt = 0; mt < 4; mt++)
                    mma16816(acc[mt][nt], ah[mt], bh);
#pragma unroll
                for (int mt = 0; mt < 4; mt++)
                    mma16816(acc[mt][nt], ah[mt], bl);
#pragma unroll
                for (int mt = 0; mt < 4; mt++)
                    mma16816(acc[mt][nt], al[mt], bh);
            }
        }
        __syncthreads();
        if (kb + 2 < nk) load_stage(st, kb + 2);
    }

    const long long cbase = p.cZ1 * zh + p.cZ2 * zl;
    const int n0 = blockIdx.x * 128 + wn + (lane & 3) * 2;
    const int m0 = blockIdx.y * 256 + wm + (lane >> 2);
#pragma unroll
    for (int mt = 0; mt < 4; mt++) {
#pragma unroll
        for (int half = 0; half < 2; half++) {
            const int m = m0 + mt * 16 + half * 8;
            const float bm = (p.biasMode == 1) ? p.bias[m] : 0.0f;
            const long long rowoff = cbase + (long long)m * p.ldC;
#pragma unroll
            for (int nt = 0; nt < 8; nt++) {
                const int n = n0 + nt * 8;
                float v0 = acc[mt][nt][half * 2 + 0] * p.alpha + bm;
                float v1 = acc[mt][nt][half * 2 + 1] * p.alpha + bm;
                if (p.biasMode == 2) { v0 += p.bias[n]; v1 += p.bias[n + 1]; }
                if (p.outMode == 0) {
                    *(float2*)(p.Cf + rowoff + n) = make_float2(v0, v1);
                } else {
                    uint32_t h, l;
                    split2(v0, v1, h, l);
                    *(uint32_t*)(p.Chi + rowoff + n) = h;
                    *(uint32_t*)(p.Clo + rowoff + n) = l;
                }
            }
        }
    }
}

// ---- fp16 1-term GEMM: 128x128x64 tile, 4 warps, 3 stages, 2 CTAs/SM -----------
__global__ void __launch_bounds__(128, 2)
hmma_gemm_f16(const __half* __restrict__ Ag, const __half* __restrict__ Bg,
              const GemmP p)
{
    extern __shared__ __align__(16) __half smh[];
    const int tid = threadIdx.x, lane = tid & 31, wid = tid >> 5;
    const int wm = (wid >> 1) * 64, wn = (wid & 1) * 64;
    const int zh = blockIdx.z >> p.zshift, zl = blockIdx.z & p.zmask;
    const long long arow0 = (long long)p.aZ1 * zh + p.aZ2 * zl + p.aConst
                            + (long long)blockIdx.y * 128;
    const long long brow0 = (long long)p.bZ1 * zh + p.bZ2 * zl + p.bConst
                            + (long long)blockIdx.x * 128;
    const __half* gA = Ag + arow0 * p.ldA;
    const __half* gB = Bg + brow0 * p.ldB;
    const uint32_t smbase = smem_u32(smh);
    const int ldA = p.ldA, ldB = p.ldB, nk = p.nk;

    auto load_stage = [&](int st, int kb) {
        const uint32_t sb = smbase + (uint32_t)st * STG_BYTES_H;
        const long long koff = (long long)kb * 64;
#pragma unroll
        for (int i = 0; i < 8; i++) {
            const int c = tid + i * 128;
            const int row = c >> 3, ch = c & 7;
            const uint32_t doff = (uint32_t)(row * PADK + ch * 8) * 2;
            cpasync16(sb + doff, gA + (long long)row * ldA + koff + ch * 8);
            cpasync16(sb + OFF_B_H + doff, gB + (long long)row * ldB + koff + ch * 8);
        }
        asm volatile("cp.async.commit_group;" ::: "memory");
    };

    load_stage(0, 0);
    load_stage(1, 1);
    load_stage(2, 2);

    float acc[4][8][4];
#pragma unroll
    for (int a = 0; a < 4; a++)
#pragma unroll
        for (int b = 0; b < 8; b++)
#pragma unroll
            for (int c = 0; c < 4; c++) acc[a][b][c] = 0.0f;

    const int krow = (lane & 3) * 2;
    const int grow = lane >> 2;

    for (int kb = 0; kb < nk; kb++) {
        asm volatile("cp.async.wait_group 2;" ::: "memory");
        __syncthreads();
        const int st = kb % 3;
        const __half* sA = smh + (size_t)st * STG_ELT_H;
        const __half* sB = sA + AH_TILE_ELT;

#pragma unroll
        for (int k16 = 0; k16 < 4; k16++) {
            const int kk = k16 * 16 + krow;
            uint32_t ah[4][4];
#pragma unroll
            for (int mt = 0; mt < 4; mt++) {
                const int r0 = (wm + mt * 16 + grow) * PADK;
                const int r1 = r0 + 8 * PADK;
                ah[mt][0] = *(const uint32_t*)(sA + r0 + kk);
                ah[mt][1] = *(const uint32_t*)(sA + r1 + kk);
                ah[mt][2] = *(const uint32_t*)(sA + r0 + kk + 8);
                ah[mt][3] = *(const uint32_t*)(sA + r1 + kk + 8);
            }
#pragma unroll
            for (int nt = 0; nt < 8; nt++) {
                const int r = (wn + nt * 8 + grow) * PADK;
                uint32_t bh[2];
                bh[0] = *(const uint32_t*)(sB + r + kk);
                bh[1] = *(const uint32_t*)(sB + r + kk + 8);
#pragma unroll
                for (int mt = 0; mt < 4; mt++)
                    mma16816h(acc[mt][nt], ah[mt], bh);
            }
        }
        __syncthreads();
        if (kb + 3 < nk) load_stage(st, kb + 3);
    }

    const long long cbase = p.cZ1 * zh + p.cZ2 * zl;
    const int n0 = blockIdx.x * 128 + wn + (lane & 3) * 2;
    const int m0 = blockIdx.y * 128 + wm + (lane >> 2);
    __half* Ch = (__half*)p.Chi;
#pragma unroll
    for (int mt = 0; mt < 4; mt++) {
#pragma unroll
        for (int half = 0; half < 2; half++) {
            const int m = m0 + mt * 16 + half * 8;
            const float bm = (p.biasMode == 1) ? p.bias[m] : 0.0f;
            const long long rowoff = cbase + (long long)m * p.ldC;
#pragma unroll
            for (int nt = 0; nt < 8; nt++) {
                const int n = n0 + nt * 8;
                float v0 = acc[mt][nt][half * 2 + 0] * p.alpha + bm;
                float v1 = acc[mt][nt][half * 2 + 1] * p.alpha + bm;
                if (p.biasMode == 2) { v0 += p.bias[n]; v1 += p.bias[n + 1]; }
                if (p.outMode == 0) {
                    *(float2*)(p.Cf + rowoff + n) = make_float2(v0, v1);
                } else {
                    *(uint32_t*)(Ch + rowoff + n) = packh2(v0, v1);
                }
            }
        }
    }
}

// ---- conversions -------------------------------------------------------------
__global__ void split_kernel(const float4* __restrict__ in, uint2* __restrict__ hi,
                             uint2* __restrict__ lo, int n4)
{
    int i = blockIdx.x * 256 + threadIdx.x;
    if (i >= n4) return;
    float4 v = in[i];
    uint32_t h0, l0, h1, l1;
    split2(v.x, v.y, h0, l0);
    split2(v.z, v.w, h1, l1);
    hi[i] = make_uint2(h0, h1);
    lo[i] = make_uint2(l0, l1);
}

__global__ void half_kernel(const float4* __restrict__ in, uint2* __restrict__ out,
                            int n4)
{
    int i = blockIdx.x * 256 + threadIdx.x;
    if (i >= n4) return;
    float4 v = in[i];
    out[i] = make_uint2(packh2(v.x, v.y), packh2(v.z, v.w));
}

__global__ void transpose_split_kernel(const float* __restrict__ x,
                                       __nv_bfloat16* __restrict__ hi,
                                       __nv_bfloat16* __restrict__ lo,
                                       __half* __restrict__ hf)
{
    __shared__ float tile[32][33];
    const int b = blockIdx.z;
    const int c0 = blockIdx.y * 32, n0 = blockIdx.x * 32;
    const int tx = threadIdx.x, ty = threadIdx.y;
    const float* xb = x + (long long)b * 16777216;
#pragma unroll
    for (int i = 0; i < 4; i++)
        tile[ty + i * 8][tx] = xb[(long long)(c0 + ty + i * 8) * 4096 + n0 + tx];
    __syncthreads();
#pragma unroll
    for (int i = 0; i < 4; i++) {
        float v = tile[tx][ty + i * 8];
        __nv_bfloat16 h = __float2bfloat16_rn(v);
        __nv_bfloat16 l = __float2bfloat16_rn(v - __bfloat162float(h));
        long long o = (long long)b * 16777216 + (long long)(n0 + ty + i * 8) * 4096 + c0 + tx;
        hi[o] = h; lo[o] = l; hf[o] = __float2half_rn(v);
    }
}

__global__ void transpose_split2_kernel(const float* __restrict__ w,
                                        __nv_bfloat16* __restrict__ hi,
                                        __nv_bfloat16* __restrict__ lo)
{
    __shared__ float tile[32][33];
    const int m0 = blockIdx.y * 32, n0 = blockIdx.x * 32;
    const int tx = threadIdx.x, ty = threadIdx.y;
#pragma unroll
    for (int i = 0; i < 4; i++)
        tile[ty + i * 8][tx] = w[(long long)(m0 + ty + i * 8) * 4096 + n0 + tx];
    __syncthreads();
#pragma unroll
    for (int i = 0; i < 4; i++) {
        float v = tile[tx][ty + i * 8];
        __nv_bfloat16 h = __float2bfloat16_rn(v);
        __nv_bfloat16 l = __float2bfloat16_rn(v - __bfloat162float(h));
        long long o = (long long)(n0 + ty + i * 8) * 4096 + m0 + tx;
        hi[o] = h; lo[o] = l;
    }
}

__global__ void wvec_kernel(const float* __restrict__ Wk,
                            const float* __restrict__ bq,
                            float* __restrict__ w)
{
    const int n = blockIdx.x * 256 + threadIdx.x;
    float acc = 0.0f;
    for (int m = 0; m < 4096; m++)
        acc += Wk[(long long)m * 4096 + n] * bq[m];
    w[n] = acc;
}

__global__ void beta_kernel(const __nv_bfloat16* __restrict__ qkv_h,
                            const __nv_bfloat16* __restrict__ qkv_l,
                            const float* __restrict__ w,
                            float* __restrict__ beta)
{
    const int bb = blockIdx.x;
    const int z = bb >> 9, d = bb & 511;
    const int b = z >> 3, h = z & 7;
    const long long row = (long long)(b * 8192 + 4096 + h * 512 + d) * 4096;
    __shared__ float red[256];
    const int t = threadIdx.x;
    float acc = 0.0f;
    for (int n = t; n < 4096; n += 256)
        acc += w[n] * (__bfloat162float(qkv_h[row + n]) + __bfloat162float(qkv_l[row + n]));
    red[t] = acc; __syncthreads();
#pragma unroll
    for (int s = 128; s > 0; s >>= 1) {
        if (t < s) red[t] += red[t + s];
        __syncthreads();
    }
    if (t == 0) beta[bb] = 0.125f * red[0];
}

// softmax over rows of 512: v = dot + dot2 + beta, output fp16
__global__ void softmax_f16_kernel(const float* __restrict__ dot,
                                   const float* __restrict__ dot2,
                                   const float* __restrict__ beta,
                                   __half* __restrict__ attn)
{
    const long long row = blockIdx.x;
    const float* p = dot + row * 512;
    const float* p2 = dot2 + row * 512;
    const float* bb = beta + ((row >> 9) << 9);
    __shared__ float red[256];
    const int t = threadIdx.x;
    float v0 = p[t] + p2[t] + bb[t];
    float v1 = p[t + 256] + p2[t + 256] + bb[t + 256];
    red[t] = fmaxf(v0, v1); __syncthreads();
#pragma unroll
    for (int s = 128; s > 0; s >>= 1) {
        if (t < s) red[t] = fmaxf(red[t], red[t + s]);
        __syncthreads();
    }
    float mx = red[0]; __syncthreads();
    float e0 = expf(v0 - mx), e1 = expf(v1 - mx);
    red[t] = e0 + e1; __syncthreads();
#pragma unroll
    for (int s = 128; s > 0; s >>= 1) {
        if (t < s) red[t] += red[t + s];
        __syncthreads();
    }
    float inv = 1.0f / red[0];
    attn[row * 512 + t]       = __float2half_rn(e0 * inv);
    attn[row * 512 + t + 256] = __float2half_rn(e1 * inv);
}

// ---- host --------------------------------------------------------------------
extern "C" void kernel_launch(void* const* d_in, const int* in_sizes, int n_in,
                              void* d_out, int out_size)
{
    const float* x    = (const float*)d_in[0];
    const float* Wqkv = (const float*)d_in[1];
    const float* bqkv = (const float*)d_in[2];
    const float* Wq   = (const float*)d_in[3];
    const float* bq   = (const float*)d_in[4];
    const float* Wk   = (const float*)d_in[5];
    const float* bk   = (const float*)d_in[6];
    const float* Wv   = (const float*)d_in[7];
    const float* bv   = (const float*)d_in[8];
    const float* Wout = (const float*)d_in[9];
    const float* bout = (const float*)d_in[10];
    float* y = (float*)d_out;
    (void)bk;

    __nv_bfloat16 *xT_h, *xT_l, *Wqkv_h, *Wqkv_l, *WqT_h, *WqT_l, *WkT_h, *WkT_l,
        *qkv_h, *qkv_l, *q2_h, *q2_l, *H_h, *H_l;
    __half *xT_f, *Wqkv_vf, *Wv_f, *Wout_f, *v_f, *v2T_f, *attn_f, *outT_f;
    float *dot, *dot2, *wvec, *beta;
    cudaGetSymbolAddress((void**)&xT_h,   g_xT_hi);   cudaGetSymbolAddress((void**)&xT_l,   g_xT_lo);
    cudaGetSymbolAddress((void**)&xT_f,   g_xT_f);
    cudaGetSymbolAddress((void**)&Wqkv_h, g_Wqkv_hi); cudaGetSymbolAddress((void**)&Wqkv_l, g_Wqkv_lo);
    cudaGetSymbolAddress((void**)&Wqkv_vf,g_Wqkv_vf);
    cudaGetSymbolAddress((void**)&WqT_h,  g_WqT_hi);  cudaGetSymbolAddress((void**)&WqT_l,  g_WqT_lo);
    cudaGetSymbolAddress((void**)&WkT_h,  g_WkT_hi);  cudaGetSymbolAddress((void**)&WkT_l,  g_WkT_lo);
    cudaGetSymbolAddress((void**)&Wv_f,   g_Wv_f);    cudaGetSymbolAddress((void**)&Wout_f, g_Wout_f);
    cudaGetSymbolAddress((void**)&qkv_h,  g_qkv_hi);  cudaGetSymbolAddress((void**)&qkv_l,  g_qkv_lo);
    cudaGetSymbolAddress((void**)&v_f,    g_v_f);
    cudaGetSymbolAddress((void**)&q2_h,   g_q2_hi);   cudaGetSymbolAddress((void**)&q2_l,   g_q2_lo);
    cudaGetSymbolAddress((void**)&H_h,    g_H_hi);    cudaGetSymbolAddress((void**)&H_l,    g_H_lo);
    cudaGetSymbolAddress((void**)&v2T_f,  g_v2T_f);
    cudaGetSymbolAddress((void**)&attn_f, g_attn_f);
    cudaGetSymbolAddress((void**)&outT_f, g_outT_f);
    cudaGetSymbolAddress((void**)&dot,    g_dot);
    cudaGetSymbolAddress((void**)&dot2,   g_dot2);
    cudaGetSymbolAddress((void**)&wvec,   g_wvec);
    cudaGetSymbolAddress((void**)&beta,   g_beta);

    cudaFuncSetAttribute(hmma_gemm, cudaFuncAttributeMaxDynamicSharedMemorySize, SMEM_REQ);
    cudaFuncSetAttribute(hmma_gemm_f16, cudaFuncAttributeMaxDynamicSharedMemorySize, SMEM_REQ_H);

    // one-time stream/event objects (host-side only; graph structure identical per call)
    static cudaStream_t s1 = nullptr;
    static cudaEvent_t e0, e1, eqk, eqg, eb, el2;
    if (!s1) {
        cudaStreamCreateWithFlags(&s1, cudaStreamNonBlocking);
        cudaEventCreateWithFlags(&e0,  cudaEventDisableTiming);
        cudaEventCreateWithFlags(&e1,  cudaEventDisableTiming);
        cudaEventCreateWithFlags(&eqk, cudaEventDisableTiming);
        cudaEventCreateWithFlags(&eqg, cudaEventDisableTiming);
        cudaEventCreateWithFlags(&eb,  cudaEventDisableTiming);
        cudaEventCreateWithFlags(&el2, cudaEventDisableTiming);
    }

    GemmP p;

    // ---- main stream: x conversion, Wqkv split, big q/k GEMM ----
    transpose_split_kernel<<<dim3(128, 128, 2), dim3(32, 8)>>>(x, xT_h, xT_l, xT_f);
    cudaEventRecord(e0, 0);                    // xT ready (for stage1v on s1)
    split_kernel<<<32768, 256>>>((const float4*)Wqkv, (uint2*)Wqkv_h, (uint2*)Wqkv_l, 8388608);
    // Stage 1qk: qkv_qk[b] = Wqkv[0:8192] @ xT[b]^T + bqkv
    p = {64, 4096, 4096, 0, 0,  0, 0, 0,  4096, 0, 0,  33554432LL, 0,
         4096, 1, 1, bqkv, nullptr, qkv_h, qkv_l, 1.0f};
    hmma_gemm<<<dim3(32, 32, 2), 256, SMEM_REQ>>>(Wqkv_h, Wqkv_l, xT_h, xT_l, p);
    cudaEventRecord(eqk, 0);

    // ---- side stream: weight conversions, H, fp16 v-chain ----
    transpose_split2_kernel<<<dim3(128, 128, 1), dim3(32, 8), 0, s1>>>(Wq, WqT_h, WqT_l);
    transpose_split2_kernel<<<dim3(128, 128, 1), dim3(32, 8), 0, s1>>>(Wk, WkT_h, WkT_l);
    half_kernel<<<16384, 256, 0, s1>>>((const float4*)Wv,   (uint2*)Wv_f,   4194304);
    half_kernel<<<16384, 256, 0, s1>>>((const float4*)Wout, (uint2*)Wout_f, 4194304);
    half_kernel<<<16384, 256, 0, s1>>>((const float4*)(Wqkv + 33554432LL), (uint2*)Wqkv_vf, 4194304);
    wvec_kernel<<<16, 256, 0, s1>>>(Wk, bq, wvec);
    // H = Wk^T Wq (once)
    p = {64, 4096, 4096, 0, 0,  0, 0, 0,  0, 0, 0,  0LL, 0LL,
         4096, 0, 1, nullptr, nullptr, H_h, H_l, 1.0f};
    hmma_gemm<<<dim3(32, 16, 1), 256, SMEM_REQ, s1>>>(WkT_h, WkT_l, WqT_h, WqT_l, p);
    cudaStreamWaitEvent(s1, e0, 0);
    // Stage 1v (fp16)
    p = {64, 4096, 4096, 0, 0,  0, 0, 0,  4096, 0, 0,  16777216LL, 0,
         4096, 1, 2, bqkv + 8192, nullptr, (__nv_bfloat16*)v_f, nullptr, 1.0f};
    hmma_gemm_f16<<<dim3(32, 32, 2), 128, SMEM_REQ_H, s1>>>(Wqkv_vf, xT_f, p);
    // Stage 2v (fp16, transposed)
    p = {64, 4096, 4096, 3, 7,  0, 0, 0,  4096, 512, 0,  16777216LL, 2097152LL,
         512, 1, 2, bv, nullptr, (__nv_bfloat16*)v2T_f, nullptr, 1.0f};
    hmma_gemm_f16<<<dim3(4, 32, 16), 128, SMEM_REQ_H, s1>>>(Wv_f, v_f, p);
    cudaEventRecord(e1, s1);                   // H, v2T, wvec, Wout_f ready
    // beta on s1 (needs qkv from main)
    cudaStreamWaitEvent(s1, eqk, 0);
    beta_kernel<<<8192, 256, 0, s1>>>(qkv_h, qkv_l, wvec, beta);
    cudaEventRecord(eb, s1);

    // ---- main: qG, logits (split-K, half 2 co-runs on s1), softmax, out ----
    cudaStreamWaitEvent(0, e1, 0);
    p = {64, 4096, 4096, 3, 7,  8192, 512, 0,  0, 0, 0,  16777216LL, 2097152LL,
         4096, 0, 1, nullptr, nullptr, q2_h, q2_l, 1.0f};
    hmma_gemm<<<dim3(32, 2, 16), 256, SMEM_REQ>>>(qkv_h, qkv_l, H_h, H_l, p);
    cudaEventRecord(eqg, 0);

    // logits half 2 on s1 (K = 2048..4095)
    cudaStreamWaitEvent(s1, eqg, 0);
    p = {32, 4096, 4096, 3, 7,  4096, 512, 0,  8192, 512, 4096,  2097152LL, 262144LL,
         512, 0, 0, nullptr, dot2, nullptr, nullptr, 0.125f};
    p.k0 = 2048;
    hmma_gemm<<<dim3(4, 2, 16), 256, SMEM_REQ, s1>>>(q2_h, q2_l, qkv_h, qkv_l, p);
    cudaEventRecord(el2, s1);

    // logits half 1 on main (K = 0..2047)
    p = {32, 4096, 4096, 3, 7,  4096, 512, 0,  8192, 512, 4096,  2097152LL, 262144LL,
         512, 0, 0, nullptr, dot, nullptr, nullptr, 0.125f};
    hmma_gemm<<<dim3(4, 2, 16), 256, SMEM_REQ>>>(q2_h, q2_l, qkv_h, qkv_l, p);

    cudaStreamWaitEvent(0, eb, 0);
    cudaStreamWaitEvent(0, el2, 0);
    softmax_f16_kernel<<<8192, 256>>>(dot, dot2, beta, attn_f);

    // Stage 5 (fp16, transposed)
    p = {8, 512, 512, 3, 7,  32768, 4096, 0,  4096, 512, 0,  16777216LL, 512LL,
         4096, 0, 2, nullptr, nullptr, (__nv_bfloat16*)outT_f, nullptr, 1.0f};
    hmma_gemm_f16<<<dim3(4, 32, 16), 128, SMEM_REQ_H>>>(v2T_f, attn_f, p);

    // Stage 6 (fp16): y = Wout @ outT^T + bout
    p = {64, 4096, 4096, 0, 0,  0, 0, 0,  4096, 0, 0,  16777216LL, 0,
         4096, 1, 0, bout, y, nullptr, nullptr, 1.0f};
    hmma_gemm_f16<<<dim3(32, 32, 2), 128, SMEM_REQ_H>>>(Wout_f, outT_f, p);

    (void)in_sizes; (void)n_in; (void)out_size;
}